// round 1
// baseline (speedup 1.0000x reference)
#include <cuda_runtime.h>
#include <math.h>

#define B_   4
#define N_   1536
#define C_   512
#define H_   8
#define D_   64
#define HID_ 1024
#define BN_  (B_*N_)    // 6144
#define BH_  (B_*H_)    // 32

__device__ __constant__ float kSCALE = 0.125f;   // d^-0.5
#define EPS_ 1e-5f

// ---------------- scratch (static device globals; no allocs allowed) ----------------
__device__ float g_h   [BN_*C_];            // LN output / reused
__device__ float g_qkv [BN_*3*C_];          // qkv projection
__device__ float g_qp  [BN_*C_];            // q' (cumulative-combined q)
__device__ float g_scores[(size_t)BH_*N_*N_];  // scores, softmaxed in place (302 MB)
__device__ float g_x2  [BN_*C_];            // x + attn_out
__device__ float g_m1  [BN_*HID_];          // fc1 output

// ---------------- reductions ----------------
__device__ __forceinline__ float blockReduceSum(float v) {
    __shared__ float sh[8];
    int lane = threadIdx.x & 31, w = threadIdx.x >> 5;
    #pragma unroll
    for (int o = 16; o > 0; o >>= 1) v += __shfl_down_sync(0xffffffffu, v, o);
    if (lane == 0) sh[w] = v;
    __syncthreads();
    if (w == 0) {
        float t = (lane < 8) ? sh[lane] : 0.f;
        #pragma unroll
        for (int o = 4; o > 0; o >>= 1) t += __shfl_down_sync(0xffffffffu, t, o);
        if (lane == 0) sh[0] = t;
    }
    __syncthreads();
    float r = sh[0];
    __syncthreads();   // protect sh reuse by subsequent calls
    return r;
}

__device__ __forceinline__ float blockReduceMax(float v) {
    __shared__ float sh[8];
    int lane = threadIdx.x & 31, w = threadIdx.x >> 5;
    #pragma unroll
    for (int o = 16; o > 0; o >>= 1) v = fmaxf(v, __shfl_down_sync(0xffffffffu, v, o));
    if (lane == 0) sh[w] = v;
    __syncthreads();
    if (w == 0) {
        float t = (lane < 8) ? sh[lane] : -INFINITY;
        #pragma unroll
        for (int o = 4; o > 0; o >>= 1) t = fmaxf(t, __shfl_down_sync(0xffffffffu, t, o));
        if (lane == 0) sh[0] = t;
    }
    __syncthreads();
    float r = sh[0];
    __syncthreads();
    return r;
}

// ---------------- LayerNorm: one block per row of 512 ----------------
__global__ __launch_bounds__(256) void ln_kernel(const float* __restrict__ x,
                                                 const float* __restrict__ g,
                                                 const float* __restrict__ b,
                                                 float* __restrict__ out) {
    size_t row = blockIdx.x;
    const float* xr = x + row * C_;
    int t = threadIdx.x;
    float a = xr[t], c = xr[t + 256];
    float s = blockReduceSum(a + c);
    float mu = s * (1.0f / C_);
    float da = a - mu, dc = c - mu;
    float vs = blockReduceSum(da * da + dc * dc);
    float rstd = rsqrtf(vs * (1.0f / C_) + EPS_);
    out[row * C_ + t]       = da * rstd * g[t]       + b[t];
    out[row * C_ + t + 256] = dc * rstd * g[t + 256] + b[t + 256];
}

// ---------------- Generic NN GEMM: C = act(A[MxK] @ B[KxN] + bias) (+resid) ----------------
// 128x128 block tile, K-tile 8, 256 threads, 8x8 per-thread register tile.
__global__ __launch_bounds__(256) void gemm128_nn(
    const float* __restrict__ A, const float* __restrict__ Bw,
    const float* __restrict__ bias, const float* __restrict__ resid,
    float* __restrict__ Cm, int M, int Nn, int K, int act)
{
    __shared__ float As[8][128];   // k-major
    __shared__ float Bs[8][128];
    int tid = threadIdx.x;
    int tx = tid & 15, ty = tid >> 4;
    int row0 = blockIdx.y * 128;
    int col0 = blockIdx.x * 128;
    int ar = tid >> 1;           // 0..127
    int ac = (tid & 1) * 4;      // 0 / 4
    int br = tid >> 5;           // 0..7
    int bc = (tid & 31) * 4;     // 0..124
    float acc[8][8];
    #pragma unroll
    for (int i = 0; i < 8; i++)
        #pragma unroll
        for (int j = 0; j < 8; j++) acc[i][j] = 0.f;

    for (int kt = 0; kt < K; kt += 8) {
        float4 av = *(const float4*)(A  + (size_t)(row0 + ar) * K  + kt + ac);
        float4 bv = *(const float4*)(Bw + (size_t)(kt + br)  * Nn + col0 + bc);
        As[ac + 0][ar] = av.x; As[ac + 1][ar] = av.y;
        As[ac + 2][ar] = av.z; As[ac + 3][ar] = av.w;
        *(float4*)(&Bs[br][bc]) = bv;
        __syncthreads();
        #pragma unroll
        for (int kk = 0; kk < 8; kk++) {
            float4 a0 = *(const float4*)(&As[kk][ty * 8]);
            float4 a1 = *(const float4*)(&As[kk][ty * 8 + 4]);
            float4 b0 = *(const float4*)(&Bs[kk][tx * 8]);
            float4 b1 = *(const float4*)(&Bs[kk][tx * 8 + 4]);
            float af[8] = {a0.x,a0.y,a0.z,a0.w,a1.x,a1.y,a1.z,a1.w};
            float bf[8] = {b0.x,b0.y,b0.z,b0.w,b1.x,b1.y,b1.z,b1.w};
            #pragma unroll
            for (int i = 0; i < 8; i++)
                #pragma unroll
                for (int j = 0; j < 8; j++)
                    acc[i][j] = fmaf(af[i], bf[j], acc[i][j]);
        }
        __syncthreads();
    }

    #pragma unroll
    for (int i = 0; i < 8; i++) {
        size_t r = row0 + ty * 8 + i;
        #pragma unroll
        for (int j = 0; j < 8; j++) {
            int c = col0 + tx * 8 + j;
            float v = acc[i][j] + bias[c];
            if (act == 1) v = 0.5f * v * (1.0f + erff(v * 0.70710678118654752f));
            if (resid) v += resid[r * Nn + c];
            Cm[r * Nn + c] = v;
        }
    }
}

// ---------------- q' combine: q'[n] = q[n] + 0.5 q[n-512] + 0.25 q[n-1024] ----------------
__global__ __launch_bounds__(256) void qprime_kernel(const float* __restrict__ qkv,
                                                     float* __restrict__ qp) {
    int idx = blockIdx.x * 256 + threadIdx.x;       // BN_*C_ total
    int c = idx & (C_ - 1);
    int bn = idx >> 9;                              // C_=512
    int n = bn % N_;
    float v = qkv[(size_t)bn * (3 * C_) + c];
    if (n >= 512)  v += 0.5f  * qkv[(size_t)(bn - 512)  * (3 * C_) + c];
    if (n >= 1024) v += 0.25f * qkv[(size_t)(bn - 1024) * (3 * C_) + c];
    qp[idx] = v;
}

// ---------------- scores = SCALE * q' @ k^T  per (b,h). 128x128 tile, K=64 ----------------
__global__ __launch_bounds__(256) void score_nt(const float* __restrict__ qp,
                                                const float* __restrict__ qkv,
                                                float* __restrict__ scores) {
    int bh = blockIdx.z;
    int b = bh >> 3, h = bh & 7;
    const float* Aq = qp  + (size_t)b * N_ * C_ + h * D_;                 // row stride C_
    const float* Bk = qkv + (size_t)b * N_ * (3 * C_) + C_ + h * D_;      // row stride 3C_
    float* Cs = scores + (size_t)bh * N_ * N_;

    __shared__ float As[8][128];
    __shared__ float Bs[8][128];
    int tid = threadIdx.x;
    int tx = tid & 15, ty = tid >> 4;
    int n0 = blockIdx.y * 128, m0 = blockIdx.x * 128;
    int ar = tid >> 1, ac = (tid & 1) * 4;
    float acc[8][8];
    #pragma unroll
    for (int i = 0; i < 8; i++)
        #pragma unroll
        for (int j = 0; j < 8; j++) acc[i][j] = 0.f;

    for (int kt = 0; kt < D_; kt += 8) {
        float4 av = *(const float4*)(Aq + (size_t)(n0 + ar) * C_       + kt + ac);
        float4 bv = *(const float4*)(Bk + (size_t)(m0 + ar) * (3 * C_) + kt + ac);
        As[ac + 0][ar] = av.x; As[ac + 1][ar] = av.y;
        As[ac + 2][ar] = av.z; As[ac + 3][ar] = av.w;
        Bs[ac + 0][ar] = bv.x; Bs[ac + 1][ar] = bv.y;
        Bs[ac + 2][ar] = bv.z; Bs[ac + 3][ar] = bv.w;
        __syncthreads();
        #pragma unroll
        for (int kk = 0; kk < 8; kk++) {
            float4 a0 = *(const float4*)(&As[kk][ty * 8]);
            float4 a1 = *(const float4*)(&As[kk][ty * 8 + 4]);
            float4 b0 = *(const float4*)(&Bs[kk][tx * 8]);
            float4 b1 = *(const float4*)(&Bs[kk][tx * 8 + 4]);
            float af[8] = {a0.x,a0.y,a0.z,a0.w,a1.x,a1.y,a1.z,a1.w};
            float bf[8] = {b0.x,b0.y,b0.z,b0.w,b1.x,b1.y,b1.z,b1.w};
            #pragma unroll
            for (int i = 0; i < 8; i++)
                #pragma unroll
                for (int j = 0; j < 8; j++)
                    acc[i][j] = fmaf(af[i], bf[j], acc[i][j]);
        }
        __syncthreads();
    }

    float sc = kSCALE;
    #pragma unroll
    for (int i = 0; i < 8; i++) {
        size_t r = n0 + ty * 8 + i;
        #pragma unroll
        for (int j = 0; j < 8; j++)
            Cs[r * N_ + m0 + tx * 8 + j] = sc * acc[i][j];
    }
}

// ---------------- in-place row softmax over 1536 elems ----------------
__global__ __launch_bounds__(256) void softmax_kernel(float* __restrict__ scores) {
    size_t row = blockIdx.x;
    float* p = scores + row * N_;
    float v[6];
    float mx = -INFINITY;
    #pragma unroll
    for (int i = 0; i < 6; i++) { v[i] = p[threadIdx.x + i * 256]; mx = fmaxf(mx, v[i]); }
    mx = blockReduceMax(mx);
    float s = 0.f;
    #pragma unroll
    for (int i = 0; i < 6; i++) { v[i] = __expf(v[i] - mx); s += v[i]; }
    s = blockReduceSum(s);
    float inv = 1.0f / s;
    #pragma unroll
    for (int i = 0; i < 6; i++) p[threadIdx.x + i * 256] = v[i] * inv;
}

// ---------------- O = P @ V, fused residual + head-transpose: x2 = x + O ----------------
// tile: 128 rows (n) x 64 cols (full d). 256 threads, 8x4 per thread, K-tile 16.
__global__ __launch_bounds__(256) void pv_kernel(const float* __restrict__ scores,
                                                 const float* __restrict__ qkv,
                                                 const float* __restrict__ x,
                                                 float* __restrict__ x2) {
    int bh = blockIdx.y;
    int b = bh >> 3, h = bh & 7;
    const float* P = scores + (size_t)bh * N_ * N_;
    const float* V = qkv + (size_t)b * N_ * (3 * C_) + 2 * C_ + h * D_;  // row stride 3C_
    int n0 = blockIdx.x * 128;

    __shared__ float Ps[16][128];   // k-major
    __shared__ float Vs[16][64];
    int tid = threadIdx.x;
    int tx = tid & 15, ty = tid >> 4;
    int ar = tid >> 2, ac = (tid & 3) * 4;     // P loads: rows 0..63 (+64), cols 16
    int vr = tid >> 4, vc = (tid & 15) * 4;    // V loads: 16x64
    float acc[8][4];
    #pragma unroll
    for (int i = 0; i < 8; i++)
        #pragma unroll
        for (int j = 0; j < 4; j++) acc[i][j] = 0.f;

    for (int kt = 0; kt < N_; kt += 16) {
        float4 p0 = *(const float4*)(P + (size_t)(n0 + ar)      * N_ + kt + ac);
        float4 p1 = *(const float4*)(P + (size_t)(n0 + 64 + ar) * N_ + kt + ac);
        Ps[ac + 0][ar] = p0.x; Ps[ac + 1][ar] = p0.y;
        Ps[ac + 2][ar] = p0.z; Ps[ac + 3][ar] = p0.w;
        Ps[ac + 0][64 + ar] = p1.x; Ps[ac + 1][64 + ar] = p1.y;
        Ps[ac + 2][64 + ar] = p1.z; Ps[ac + 3][64 + ar] = p1.w;
        float4 vv = *(const float4*)(V + (size_t)(kt + vr) * (3 * C_) + vc);
        *(float4*)(&Vs[vr][vc]) = vv;
        __syncthreads();
        #pragma unroll
        for (int kk = 0; kk < 16; kk++) {
            float4 a0 = *(const float4*)(&Ps[kk][ty * 8]);
            float4 a1 = *(const float4*)(&Ps[kk][ty * 8 + 4]);
            float4 b0 = *(const float4*)(&Vs[kk][tx * 4]);
            float af[8] = {a0.x,a0.y,a0.z,a0.w,a1.x,a1.y,a1.z,a1.w};
            float bf[4] = {b0.x,b0.y,b0.z,b0.w};
            #pragma unroll
            for (int i = 0; i < 8; i++)
                #pragma unroll
                for (int j = 0; j < 4; j++)
                    acc[i][j] = fmaf(af[i], bf[j], acc[i][j]);
        }
        __syncthreads();
    }

    #pragma unroll
    for (int i = 0; i < 8; i++) {
        int n = n0 + ty * 8 + i;
        size_t base = ((size_t)(b * N_ + n)) * C_ + h * D_ + tx * 4;
        #pragma unroll
        for (int j = 0; j < 4; j++)
            x2[base + j] = x[base + j] + acc[i][j];
    }
}

// ---------------- launch ----------------
extern "C" void kernel_launch(void* const* d_in, const int* in_sizes, int n_in,
                              void* d_out, int out_size) {
    const float* x      = (const float*)d_in[0];
    const float* ln1_g  = (const float*)d_in[1];
    const float* ln1_b  = (const float*)d_in[2];
    const float* qkv_w  = (const float*)d_in[3];
    const float* qkv_b  = (const float*)d_in[4];
    const float* ln2_g  = (const float*)d_in[5];
    const float* ln2_b  = (const float*)d_in[6];
    const float* fc1_w  = (const float*)d_in[7];
    const float* fc1_b  = (const float*)d_in[8];
    const float* fc2_w  = (const float*)d_in[9];
    const float* fc2_b  = (const float*)d_in[10];
    float* out = (float*)d_out;

    float *h, *qkv, *qp, *scores, *x2, *m1;
    cudaGetSymbolAddress((void**)&h,      g_h);
    cudaGetSymbolAddress((void**)&qkv,    g_qkv);
    cudaGetSymbolAddress((void**)&qp,     g_qp);
    cudaGetSymbolAddress((void**)&scores, g_scores);
    cudaGetSymbolAddress((void**)&x2,     g_x2);
    cudaGetSymbolAddress((void**)&m1,     g_m1);

    // 1. LN1
    ln_kernel<<<BN_, 256>>>(x, ln1_g, ln1_b, h);
    // 2. qkv = h @ qkv_w + b       (6144 x 1536 x 512)
    gemm128_nn<<<dim3(3 * C_ / 128, BN_ / 128), 256>>>(h, qkv_w, qkv_b, nullptr, qkv,
                                                       BN_, 3 * C_, C_, 0);
    // 3. q' combine (linearized cumulative-attn trick)
    qprime_kernel<<<BN_ * C_ / 256, 256>>>(qkv, qp);
    // 4. scores = scale * q' @ k^T  per (b,h)
    score_nt<<<dim3(N_ / 128, N_ / 128, BH_), 256>>>(qp, qkv, scores);
    // 5. softmax in place
    softmax_kernel<<<BH_ * N_, 256>>>(scores);
    // 6. x2 = x + P @ V (with head transpose)
    pv_kernel<<<dim3(N_ / 128, BH_), 256>>>(scores, qkv, x, x2);
    // 7. LN2
    ln_kernel<<<BN_, 256>>>(x2, ln2_g, ln2_b, h);
    // 8. m1 = gelu(h @ fc1_w + b)   (6144 x 1024 x 512)
    gemm128_nn<<<dim3(HID_ / 128, BN_ / 128), 256>>>(h, fc1_w, fc1_b, nullptr, m1,
                                                     BN_, HID_, C_, 1);
    // 9. out = x2 + m1 @ fc2_w + b  (6144 x 512 x 1024)
    gemm128_nn<<<dim3(C_ / 128, BN_ / 128), 256>>>(m1, fc2_w, fc2_b, x2, out,
                                                   BN_, C_, HID_, 0);
}

// round 3
// speedup vs baseline: 2.6543x; 2.6543x over previous
#include <cuda_runtime.h>
#include <math.h>
#include <stdint.h>

#define B_   4
#define N_   1536
#define C_   512
#define H_   8
#define D_   64
#define HID_ 1024
#define BN_  (B_*N_)    // 6144
#define BH_  (B_*H_)    // 32
#define EPS_ 1e-5f

// ---------------- scratch (static device globals) ----------------
__device__ float g_h   [BN_*C_];
__device__ float g_qkv [BN_*3*C_];
__device__ float g_qp  [BN_*C_];
__device__ float g_scores[(size_t)BH_*N_*N_];
__device__ float g_x2  [BN_*C_];
__device__ float g_m1  [BN_*HID_];

// ---------------- helpers ----------------
__device__ __forceinline__ uint32_t f2tf32(float f) {
    uint32_t u; asm("cvt.rna.tf32.f32 %0, %1;" : "=r"(u) : "f"(f)); return u;
}

__device__ __forceinline__ void mma_tf32(float c[4], uint32_t a0, uint32_t a1,
                                         uint32_t a2, uint32_t a3,
                                         uint32_t b0, uint32_t b1) {
    asm volatile(
        "mma.sync.aligned.m16n8k8.row.col.f32.tf32.tf32.f32 "
        "{%0,%1,%2,%3}, {%4,%5,%6,%7}, {%8,%9}, {%0,%1,%2,%3};"
        : "+f"(c[0]), "+f"(c[1]), "+f"(c[2]), "+f"(c[3])
        : "r"(a0), "r"(a1), "r"(a2), "r"(a3), "r"(b0), "r"(b1));
}

// ================= TF32 mma.sync GEMM: D = A @ op(B) =================
// A [M,K] row-major. TRANSB=1: B given as [N,K] rows (we compute A B^T).
//                    TRANSB=0: B given as [K,N] rows (we compute A B).
// Block tile 128 x NT, 8 warps (4m x 2n), warp tile 32 x NT/2, K-tile 32.
// EPI: 0 +bias | 1 gelu(+bias) | 2 +bias+resid | 3 *0.125 (scores, batched z)
//      4 +resid (pv, batched z)
template<int NT, int EPI, int TRANSB>
__global__ __launch_bounds__(256) void gemm_mma(
    const float* __restrict__ Abase, int lda,
    const float* __restrict__ Bbase, int ldb,
    float* __restrict__ Cbase, int ldc,
    const float* __restrict__ bias,
    const float* __restrict__ resid, int K)
{
    constexpr int NJ  = NT / 16;       // n-tiles (8 wide) per warp
    constexpr int BKN = NT + 8;        // [k][n] stride for NN B tiles
    __shared__ uint32_t As[128 * 36];
    __shared__ uint32_t Bs[TRANSB ? (NT * 36) : (32 * BKN)];

    int tid = threadIdx.x, wid = tid >> 5, lane = tid & 31;
    int z = blockIdx.z;

    const float* A; const float* Bm; float* Cm; const float* Rm = resid;
    if (EPI == 3) {                 // scores: A = q' slice, B = k rows inside qkv
        int b = z >> 3, h = z & 7;
        A  = Abase + (size_t)b * N_ * C_ + h * D_;
        Bm = Bbase + (size_t)b * N_ * (3 * C_) + C_ + h * D_;
        Cm = Cbase + (size_t)z * N_ * N_;
    } else if (EPI == 4) {          // pv: A = P, B = V rows inside qkv
        int b = z >> 3, h = z & 7;
        A  = Abase + (size_t)z * N_ * N_;
        Bm = Bbase + (size_t)b * N_ * (3 * C_) + 2 * C_ + h * D_;
        size_t coff = (size_t)b * N_ * C_ + (size_t)h * D_;
        Cm = Cbase + coff;
        Rm = resid + coff;
    } else {
        A = Abase; Bm = Bbase; Cm = Cbase;
    }
    int m0 = blockIdx.y * 128, n0 = blockIdx.x * NT;
    A += (size_t)m0 * lda;
    if (TRANSB) Bm += (size_t)n0 * ldb;
    else        Bm += n0;

    int wm = wid & 3, wn = wid >> 2;           // 4 x 2 warp grid
    constexpr int WN = NT / 2;

    float acc[2][NJ][4];
    #pragma unroll
    for (int i = 0; i < 2; i++)
        #pragma unroll
        for (int j = 0; j < NJ; j++)
            #pragma unroll
            for (int q = 0; q < 4; q++) acc[i][j][q] = 0.f;

    int T = K >> 5;
    for (int kt = 0; kt < T; kt++) {
        if (kt) __syncthreads();
        // ---- A tile: [128][32] -> As[row][k], stride 36 ----
        #pragma unroll
        for (int it = 0; it < 4; it++) {
            int idx = tid + it * 256;
            int r = idx >> 3, c4 = (idx & 7) * 4;
            float4 v = *(const float4*)(A + (size_t)r * lda + kt * 32 + c4);
            uint4 u = make_uint4(f2tf32(v.x), f2tf32(v.y), f2tf32(v.z), f2tf32(v.w));
            *(uint4*)&As[r * 36 + c4] = u;
        }
        // ---- B tile ----
        if (TRANSB) {   // rows n, k-major -> Bs[n][k], stride 36
            #pragma unroll
            for (int it = 0; it < NT * 8 / 256; it++) {
                int idx = tid + it * 256;
                int r = idx >> 3, c4 = (idx & 7) * 4;
                float4 v = *(const float4*)(Bm + (size_t)r * ldb + kt * 32 + c4);
                uint4 u = make_uint4(f2tf32(v.x), f2tf32(v.y), f2tf32(v.z), f2tf32(v.w));
                *(uint4*)&Bs[r * 36 + c4] = u;
            }
        } else {        // rows k, n-major -> Bs[k][n], stride NT+8
            constexpr int NB4 = NT / 4;
            #pragma unroll
            for (int it = 0; it < 32 * NB4 / 256; it++) {
                int idx = tid + it * 256;
                int n4 = (idx & (NB4 - 1)) * 4;
                int k  = idx / NB4;
                float4 v = *(const float4*)(Bm + (size_t)(kt * 32 + k) * ldb + n4);
                uint4 u = make_uint4(f2tf32(v.x), f2tf32(v.y), f2tf32(v.z), f2tf32(v.w));
                *(uint4*)&Bs[k * BKN + n4] = u;
            }
        }
        __syncthreads();

        // ---- compute: 4 k-steps of 8 ----
        int r0 = wm * 32 + (lane >> 2);
        int cb = wn * WN + (lane >> 2);
        #pragma unroll
        for (int ks = 0; ks < 4; ks++) {
            int k0 = ks * 8;
            int kk = k0 + (lane & 3);
            uint32_t a[2][4];
            #pragma unroll
            for (int i = 0; i < 2; i++) {
                int rr = r0 + i * 16;
                a[i][0] = As[rr * 36 + kk];
                a[i][1] = As[(rr + 8) * 36 + kk];
                a[i][2] = As[rr * 36 + kk + 4];
                a[i][3] = As[(rr + 8) * 36 + kk + 4];
            }
            uint32_t b[NJ][2];
            #pragma unroll
            for (int j = 0; j < NJ; j++) {
                int cc = cb + j * 8;
                if (TRANSB) {
                    b[j][0] = Bs[cc * 36 + kk];
                    b[j][1] = Bs[cc * 36 + kk + 4];
                } else {
                    b[j][0] = Bs[kk * BKN + cc];
                    b[j][1] = Bs[(kk + 4) * BKN + cc];
                }
            }
            #pragma unroll
            for (int i = 0; i < 2; i++)
                #pragma unroll
                for (int j = 0; j < NJ; j++)
                    mma_tf32(acc[i][j], a[i][0], a[i][1], a[i][2], a[i][3],
                             b[j][0], b[j][1]);
        }
    }

    // ---- epilogue: fragment regs -> gmem, fused ops ----
    int rbase = m0 + wm * 32 + (lane >> 2);
    int cbase = n0 + wn * WN + 2 * (lane & 3);
    #pragma unroll
    for (int i = 0; i < 2; i++) {
        #pragma unroll
        for (int half = 0; half < 2; half++) {       // c0,c1 then c2,c3 (row+8)
            size_t r = (size_t)(rbase + i * 16 + half * 8);
            float* crow = Cm + r * ldc;
            const float* rrow = (EPI == 2 || EPI == 4) ? (Rm + r * ldc) : nullptr;
            #pragma unroll
            for (int j = 0; j < NJ; j++) {
                int c = cbase + j * 8;
                float v0 = acc[i][j][half * 2 + 0];
                float v1 = acc[i][j][half * 2 + 1];
                if (EPI == 0) {
                    v0 += bias[c]; v1 += bias[c + 1];
                } else if (EPI == 1) {
                    v0 += bias[c]; v1 += bias[c + 1];
                    v0 = 0.5f * v0 * (1.0f + erff(v0 * 0.70710678118654752f));
                    v1 = 0.5f * v1 * (1.0f + erff(v1 * 0.70710678118654752f));
                } else if (EPI == 2) {
                    v0 += bias[c]     + rrow[c];
                    v1 += bias[c + 1] + rrow[c + 1];
                } else if (EPI == 3) {
                    v0 *= 0.125f; v1 *= 0.125f;
                } else if (EPI == 4) {
                    v0 += rrow[c]; v1 += rrow[c + 1];
                }
                float2 o; o.x = v0; o.y = v1;
                *(float2*)(crow + c) = o;
            }
        }
    }
}

// ---------------- reductions ----------------
__device__ __forceinline__ float blockReduceSum(float v) {
    __shared__ float sh[8];
    int lane = threadIdx.x & 31, w = threadIdx.x >> 5;
    #pragma unroll
    for (int o = 16; o > 0; o >>= 1) v += __shfl_down_sync(0xffffffffu, v, o);
    if (lane == 0) sh[w] = v;
    __syncthreads();
    if (w == 0) {
        float t = (lane < 8) ? sh[lane] : 0.f;
        #pragma unroll
        for (int o = 4; o > 0; o >>= 1) t += __shfl_down_sync(0xffffffffu, t, o);
        if (lane == 0) sh[0] = t;
    }
    __syncthreads();
    float r = sh[0];
    __syncthreads();
    return r;
}
__device__ __forceinline__ float blockReduceMax(float v) {
    __shared__ float sh[8];
    int lane = threadIdx.x & 31, w = threadIdx.x >> 5;
    #pragma unroll
    for (int o = 16; o > 0; o >>= 1) v = fmaxf(v, __shfl_down_sync(0xffffffffu, v, o));
    if (lane == 0) sh[w] = v;
    __syncthreads();
    if (w == 0) {
        float t = (lane < 8) ? sh[lane] : -INFINITY;
        #pragma unroll
        for (int o = 4; o > 0; o >>= 1) t = fmaxf(t, __shfl_down_sync(0xffffffffu, t, o));
        if (lane == 0) sh[0] = t;
    }
    __syncthreads();
    float r = sh[0];
    __syncthreads();
    return r;
}

// ---------------- LayerNorm ----------------
__global__ __launch_bounds__(256) void ln_kernel(const float* __restrict__ x,
                                                 const float* __restrict__ g,
                                                 const float* __restrict__ b,
                                                 float* __restrict__ out) {
    size_t row = blockIdx.x;
    const float* xr = x + row * C_;
    int t = threadIdx.x;
    float a = xr[t], c = xr[t + 256];
    float s = blockReduceSum(a + c);
    float mu = s * (1.0f / C_);
    float da = a - mu, dc = c - mu;
    float vs = blockReduceSum(da * da + dc * dc);
    float rstd = rsqrtf(vs * (1.0f / C_) + EPS_);
    out[row * C_ + t]       = da * rstd * g[t]       + b[t];
    out[row * C_ + t + 256] = dc * rstd * g[t + 256] + b[t + 256];
}

// ---------------- q' combine ----------------
__global__ __launch_bounds__(256) void qprime_kernel(const float* __restrict__ qkv,
                                                     float* __restrict__ qp) {
    int idx = blockIdx.x * 256 + threadIdx.x;
    int c = idx & (C_ - 1);
    int bn = idx >> 9;
    int n = bn % N_;
    float v = qkv[(size_t)bn * (3 * C_) + c];
    if (n >= 512)  v += 0.5f  * qkv[(size_t)(bn - 512)  * (3 * C_) + c];
    if (n >= 1024) v += 0.25f * qkv[(size_t)(bn - 1024) * (3 * C_) + c];
    qp[idx] = v;
}

// ---------------- in-place row softmax ----------------
__global__ __launch_bounds__(256) void softmax_kernel(float* __restrict__ scores) {
    size_t row = blockIdx.x;
    float* p = scores + row * N_;
    float v[6];
    float mx = -INFINITY;
    #pragma unroll
    for (int i = 0; i < 6; i++) { v[i] = p[threadIdx.x + i * 256]; mx = fmaxf(mx, v[i]); }
    mx = blockReduceMax(mx);
    float s = 0.f;
    #pragma unroll
    for (int i = 0; i < 6; i++) { v[i] = __expf(v[i] - mx); s += v[i]; }
    s = blockReduceSum(s);
    float inv = 1.0f / s;
    #pragma unroll
    for (int i = 0; i < 6; i++) p[threadIdx.x + i * 256] = v[i] * inv;
}

// ---------------- launch ----------------
extern "C" void kernel_launch(void* const* d_in, const int* in_sizes, int n_in,
                              void* d_out, int out_size) {
    const float* x      = (const float*)d_in[0];
    const float* ln1_g  = (const float*)d_in[1];
    const float* ln1_b  = (const float*)d_in[2];
    const float* qkv_w  = (const float*)d_in[3];
    const float* qkv_b  = (const float*)d_in[4];
    const float* ln2_g  = (const float*)d_in[5];
    const float* ln2_b  = (const float*)d_in[6];
    const float* fc1_w  = (const float*)d_in[7];
    const float* fc1_b  = (const float*)d_in[8];
    const float* fc2_w  = (const float*)d_in[9];
    const float* fc2_b  = (const float*)d_in[10];
    float* out = (float*)d_out;

    float *h, *qkv, *qp, *scores, *x2, *m1;
    cudaGetSymbolAddress((void**)&h,      g_h);
    cudaGetSymbolAddress((void**)&qkv,    g_qkv);
    cudaGetSymbolAddress((void**)&qp,     g_qp);
    cudaGetSymbolAddress((void**)&scores, g_scores);
    cudaGetSymbolAddress((void**)&x2,     g_x2);
    cudaGetSymbolAddress((void**)&m1,     g_m1);

    // 1. LN1
    ln_kernel<<<BN_, 256>>>(x, ln1_g, ln1_b, h);
    // 2. qkv = h @ qkv_w + b          (NN: B = [512,1536])
    gemm_mma<128, 0, 0><<<dim3(3 * C_ / 128, BN_ / 128, 1), 256>>>(
        h, C_, qkv_w, 3 * C_, qkv, 3 * C_, qkv_b, nullptr, C_);
    // 3. q' combine
    qprime_kernel<<<BN_ * C_ / 256, 256>>>(qkv, qp);
    // 4. scores = 0.125 * q' @ k^T    (NT, batched over bh)
    gemm_mma<128, 3, 1><<<dim3(N_ / 128, N_ / 128, BH_), 256>>>(
        qp, C_, qkv, 3 * C_, scores, N_, nullptr, nullptr, D_);
    // 5. softmax
    softmax_kernel<<<BH_ * N_, 256>>>(scores);
    // 6. x2 = x + P @ V               (NN, batched over bh)
    gemm_mma<64, 4, 0><<<dim3(1, N_ / 128, BH_), 256>>>(
        scores, N_, qkv, 3 * C_, x2, C_, nullptr, x, N_);
    // 7. LN2
    ln_kernel<<<BN_, 256>>>(x2, ln2_g, ln2_b, h);
    // 8. m1 = gelu(h @ fc1_w + b)     (NN)
    gemm_mma<128, 1, 0><<<dim3(HID_ / 128, BN_ / 128, 1), 256>>>(
        h, C_, fc1_w, HID_, m1, HID_, fc1_b, nullptr, C_);
    // 9. out = x2 + m1 @ fc2_w + b    (NN)
    gemm_mma<128, 2, 0><<<dim3(C_ / 128, BN_ / 128, 1), 256>>>(
        m1, HID_, fc2_w, C_, out, C_, fc2_b, x2, HID_);
}

// round 4
// speedup vs baseline: 6.7467x; 2.5418x over previous
#include <cuda_runtime.h>
#include <cuda_fp16.h>
#include <math.h>
#include <stdint.h>

#define B_   4
#define N_   1536
#define C_   512
#define H_   8
#define D_   64
#define HID_ 1024
#define BN_  (B_*N_)    // 6144
#define BH_  (B_*H_)    // 32
#define EPS_ 1e-5f

// ---------------- scratch ----------------
__device__ __half g_h   [BN_*C_];
__device__ __half g_qkv [BN_*3*C_];
__device__ __half g_qp  [BN_*C_];
__device__ float  g_x2  [BN_*C_];
__device__ __half g_m1  [BN_*HID_];
__device__ __half g_w1  [C_*3*C_];    // qkv_w f16
__device__ __half g_w2  [C_*HID_];    // fc1_w f16
__device__ __half g_w3  [HID_*C_];    // fc2_w f16

// ---------------- asm helpers ----------------
#define LDSM4(d0,d1,d2,d3,addr) \
    asm volatile("ldmatrix.sync.aligned.m8n8.x4.shared.b16 {%0,%1,%2,%3}, [%4];" \
        : "=r"(d0),"=r"(d1),"=r"(d2),"=r"(d3) : "r"(addr))
#define LDSM4T(d0,d1,d2,d3,addr) \
    asm volatile("ldmatrix.sync.aligned.m8n8.x4.trans.shared.b16 {%0,%1,%2,%3}, [%4];" \
        : "=r"(d0),"=r"(d1),"=r"(d2),"=r"(d3) : "r"(addr))

__device__ __forceinline__ void mma_f16(float c[4], uint32_t a0, uint32_t a1,
                                        uint32_t a2, uint32_t a3,
                                        uint32_t b0, uint32_t b1) {
    asm volatile(
        "mma.sync.aligned.m16n8k16.row.col.f32.f16.f16.f32 "
        "{%0,%1,%2,%3}, {%4,%5,%6,%7}, {%8,%9}, {%0,%1,%2,%3};"
        : "+f"(c[0]), "+f"(c[1]), "+f"(c[2]), "+f"(c[3])
        : "r"(a0), "r"(a1), "r"(a2), "r"(a3), "r"(b0), "r"(b1));
}
__device__ __forceinline__ uint32_t packh2(float lo, float hi) {
    __half2 h = __float22half2_rn(make_float2(lo, hi));
    return *(uint32_t*)&h;
}
__device__ __forceinline__ uint32_t smem_u32(const void* p) {
    return (uint32_t)__cvta_generic_to_shared(p);
}

// ================= dense fp16 GEMM: C = epi(A @ B + bias) =================
// A f16 [M,K] rm, B f16 [K,N] rm. 128x128 tile, kt=32, 8 warps (4m x 2n).
// EPI: 0 -> f16 out (+bias) | 1 -> f16 out gelu(+bias) | 2 -> f32 out (+bias+resid)
#define ASTR 40    // halves per A smem row (32 + 8 pad), 80B
#define BSTR 136   // halves per B smem row (128 + 8 pad), 272B
template<int EPI>
__global__ __launch_bounds__(256) void gemm_h(
    const __half* __restrict__ A, int lda,
    const __half* __restrict__ Bw, int ldb,
    void* __restrict__ Cout, int ldc,
    const float* __restrict__ bias,
    const float* __restrict__ resid, int K)
{
    __shared__ __half As[2][128 * ASTR];
    __shared__ __half Bs[2][32 * BSTR];

    int tid = threadIdx.x, wid = tid >> 5, lane = tid & 31;
    int wm = wid & 3, wn = wid >> 2;
    int m0 = blockIdx.y * 128, n0 = blockIdx.x * 128;

    float acc[2][8][4];
    #pragma unroll
    for (int i = 0; i < 2; i++)
        #pragma unroll
        for (int j = 0; j < 8; j++)
            #pragma unroll
            for (int q = 0; q < 4; q++) acc[i][j][q] = 0.f;

    // fill index precompute
    int ar = (tid >> 2), ac = (tid & 3);          // +256: ar+64
    int bk = (tid >> 4), bc = (tid & 15);         // +256: bk+16
    const __half* Ag = A + (size_t)(m0 + ar) * lda + ac * 8;
    const __half* Bg = Bw + (size_t)bk * ldb + n0 + bc * 8;

    uint4 a_r[2], b_r[2];
    // prologue: tile 0
    a_r[0] = *(const uint4*)(Ag);
    a_r[1] = *(const uint4*)(Ag + (size_t)64 * lda);
    b_r[0] = *(const uint4*)(Bg);
    b_r[1] = *(const uint4*)(Bg + (size_t)16 * ldb);
    *(uint4*)&As[0][ar * ASTR + ac * 8] = a_r[0];
    *(uint4*)&As[0][(ar + 64) * ASTR + ac * 8] = a_r[1];
    *(uint4*)&Bs[0][bk * BSTR + bc * 8] = b_r[0];
    *(uint4*)&Bs[0][(bk + 16) * BSTR + bc * 8] = b_r[1];
    __syncthreads();

    int T = K >> 5;
    // ldsm lane addressing
    int l15 = lane & 15, lhi = lane >> 4;
    for (int kt = 0; kt < T; kt++) {
        int buf = kt & 1;
        if (kt + 1 < T) {
            const __half* Ag2 = Ag + (kt + 1) * 32;
            const __half* Bg2 = Bg + (size_t)(kt + 1) * 32 * ldb;
            a_r[0] = *(const uint4*)(Ag2);
            a_r[1] = *(const uint4*)(Ag2 + (size_t)64 * lda);
            b_r[0] = *(const uint4*)(Bg2);
            b_r[1] = *(const uint4*)(Bg2 + (size_t)16 * ldb);
        }
        uint32_t sA = smem_u32(&As[buf][0]);
        uint32_t sB = smem_u32(&Bs[buf][0]);
        // A frags: 2 m-tiles x 2 k-steps
        uint32_t af[2][2][4];
        #pragma unroll
        for (int i = 0; i < 2; i++) {
            uint32_t base = sA + ((wm * 32 + i * 16 + l15) * ASTR + lhi * 8) * 2;
            #pragma unroll
            for (int s = 0; s < 2; s++)
                LDSM4(af[i][s][0], af[i][s][1], af[i][s][2], af[i][s][3],
                      base + s * 32);
        }
        #pragma unroll
        for (int s = 0; s < 2; s++) {
            uint32_t bbase = sB + ((s * 16 + l15) * BSTR + wn * 64 + lhi * 8) * 2;
            #pragma unroll
            for (int jj = 0; jj < 4; jj++) {
                uint32_t b0, b1, b2, b3;
                LDSM4T(b0, b1, b2, b3, bbase + jj * 32);
                #pragma unroll
                for (int i = 0; i < 2; i++) {
                    mma_f16(acc[i][2 * jj],     af[i][s][0], af[i][s][1], af[i][s][2], af[i][s][3], b0, b1);
                    mma_f16(acc[i][2 * jj + 1], af[i][s][0], af[i][s][1], af[i][s][2], af[i][s][3], b2, b3);
                }
            }
        }
        if (kt + 1 < T) {
            int nb = (kt + 1) & 1;
            *(uint4*)&As[nb][ar * ASTR + ac * 8] = a_r[0];
            *(uint4*)&As[nb][(ar + 64) * ASTR + ac * 8] = a_r[1];
            *(uint4*)&Bs[nb][bk * BSTR + bc * 8] = b_r[0];
            *(uint4*)&Bs[nb][(bk + 16) * BSTR + bc * 8] = b_r[1];
        }
        __syncthreads();
    }

    // epilogue
    int rq = lane >> 2, cq = lane & 3;
    #pragma unroll
    for (int i = 0; i < 2; i++) {
        #pragma unroll
        for (int half = 0; half < 2; half++) {
            size_t r = (size_t)(m0 + wm * 32 + i * 16 + rq + half * 8);
            #pragma unroll
            for (int j = 0; j < 8; j++) {
                int c = n0 + wn * 64 + j * 8 + 2 * cq;
                float v0 = acc[i][j][half * 2 + 0];
                float v1 = acc[i][j][half * 2 + 1];
                if (EPI == 0) {
                    v0 += bias[c]; v1 += bias[c + 1];
                    *(uint32_t*)((__half*)Cout + r * ldc + c) = packh2(v0, v1);
                } else if (EPI == 1) {
                    v0 += bias[c]; v1 += bias[c + 1];
                    v0 = 0.5f * v0 * (1.0f + erff(v0 * 0.70710678118654752f));
                    v1 = 0.5f * v1 * (1.0f + erff(v1 * 0.70710678118654752f));
                    *(uint32_t*)((__half*)Cout + r * ldc + c) = packh2(v0, v1);
                } else {
                    const float* rr = resid + r * ldc;
                    float2 o;
                    o.x = v0 + bias[c]     + rr[c];
                    o.y = v1 + bias[c + 1] + rr[c + 1];
                    *(float2*)((float*)Cout + r * ldc + c) = o;
                }
            }
        }
    }
}

// ================= fused flash attention =================
// per block: 128 query rows of one (b,h); loops 24 chunks of 64 keys.
// x2 = x + softmax(q' k^T) v   (scale folded into q')
#define FSTR 72   // halves per smem row (64 + 8 pad), 144B
__global__ __launch_bounds__(256) void flash_kernel(
    const __half* __restrict__ qp, const __half* __restrict__ qkv,
    const float* __restrict__ x, float* __restrict__ x2)
{
    __shared__ __half Qs[128 * FSTR];
    __shared__ __half Ks[64 * FSTR];
    __shared__ __half Vs[64 * FSTR];

    int tid = threadIdx.x, wid = tid >> 5, lane = tid & 31;
    int bh = blockIdx.y, b = bh >> 3, h = bh & 7;
    int q0 = blockIdx.x * 128;
    int l15 = lane & 15, lhi = lane >> 4;
    int rq = lane >> 2, cq = lane & 3;

    // ---- load Q tile ----
    {
        int row = tid >> 3, c = tid & 7;           // + it*32 rows
        #pragma unroll
        for (int it = 0; it < 4; it++) {
            int r = row + it * 32;
            uint4 v = *(const uint4*)(qp + ((size_t)(b * N_ + q0 + r)) * C_ + h * D_ + c * 8);
            *(uint4*)&Qs[r * FSTR + c * 8] = v;
        }
    }
    __syncthreads();

    // Q a-frags: rows wid*16.., 4 k-steps (d=64)
    uint32_t aq[4][4];
    {
        uint32_t base = smem_u32(Qs) + ((wid * 16 + l15) * FSTR + lhi * 8) * 2;
        #pragma unroll
        for (int s = 0; s < 4; s++)
            LDSM4(aq[s][0], aq[s][1], aq[s][2], aq[s][3], base + s * 32);
    }

    float oacc[8][4];
    #pragma unroll
    for (int j = 0; j < 8; j++)
        #pragma unroll
        for (int q = 0; q < 4; q++) oacc[j][q] = 0.f;
    float mrun[2] = {-INFINITY, -INFINITY};
    float lrun[2] = {0.f, 0.f};

    // ldsm bases (byte offsets added per use)
    uint32_t kbase = smem_u32(Ks) + ((((lane >> 4) & 1) * 8 + (lane & 7)) * FSTR + ((lane >> 3) & 1) * 8) * 2;
    uint32_t vbase = smem_u32(Vs) + (l15 * FSTR + lhi * 8) * 2;

    // KV fill indices
    int fr = (tid >> 3) & 31, fc = tid & 7, ft = tid >> 8;   // ft always 0; use iter
    const __half* qkvb = qkv + (size_t)(b * N_) * (3 * C_) + h * D_;

    for (int kc = 0; kc < 24; kc++) {
        int kb = kc * 64;
        // fill Ks, Vs: 4 iters x 256 thr = 1024 chunks (2 tensors x 64 rows x 8)
        #pragma unroll
        for (int it = 0; it < 4; it++) {
            int idx = tid + it * 256;
            int tens = idx >> 9;              // 0 = K, 1 = V
            int row = (idx >> 3) & 63;
            int c = idx & 7;
            uint4 v = *(const uint4*)(qkvb + (size_t)(kb + row) * (3 * C_)
                                      + (tens ? 2 * C_ : C_) + c * 8);
            if (tens) *(uint4*)&Vs[row * FSTR + c * 8] = v;
            else      *(uint4*)&Ks[row * FSTR + c * 8] = v;
        }
        __syncthreads();

        // ---- S = Q K^T : 8 key n-tiles x 4 d k-steps ----
        float sacc[8][4];
        #pragma unroll
        for (int j = 0; j < 8; j++)
            #pragma unroll
            for (int q = 0; q < 4; q++) sacc[j][q] = 0.f;
        #pragma unroll
        for (int s = 0; s < 4; s++) {
            #pragma unroll
            for (int jj = 0; jj < 4; jj++) {
                uint32_t b0, b1, b2, b3;
                LDSM4(b0, b1, b2, b3, kbase + jj * (16 * FSTR * 2) + s * 32);
                mma_f16(sacc[2 * jj],     aq[s][0], aq[s][1], aq[s][2], aq[s][3], b0, b1);
                mma_f16(sacc[2 * jj + 1], aq[s][0], aq[s][1], aq[s][2], aq[s][3], b2, b3);
            }
        }

        // ---- online softmax (rows rq, rq+8) ----
        #pragma unroll
        for (int hf = 0; hf < 2; hf++) {
            int r0 = 2 * hf, r1 = 2 * hf + 1;
            float tmax = -INFINITY;
            #pragma unroll
            for (int j = 0; j < 8; j++)
                tmax = fmaxf(tmax, fmaxf(sacc[j][r0], sacc[j][r1]));
            tmax = fmaxf(tmax, __shfl_xor_sync(0xffffffffu, tmax, 1));
            tmax = fmaxf(tmax, __shfl_xor_sync(0xffffffffu, tmax, 2));
            float mnew = fmaxf(mrun[hf], tmax);
            float sc = __expf(mrun[hf] - mnew);
            float tsum = 0.f;
            #pragma unroll
            for (int j = 0; j < 8; j++) {
                float p0 = __expf(sacc[j][r0] - mnew);
                float p1 = __expf(sacc[j][r1] - mnew);
                sacc[j][r0] = p0; sacc[j][r1] = p1;
                tsum += p0 + p1;
            }
            tsum += __shfl_xor_sync(0xffffffffu, tsum, 1);
            tsum += __shfl_xor_sync(0xffffffffu, tsum, 2);
            lrun[hf] = lrun[hf] * sc + tsum;
            mrun[hf] = mnew;
            #pragma unroll
            for (int j = 0; j < 8; j++) { oacc[j][r0] *= sc; oacc[j][r1] *= sc; }
        }

        // ---- O += P V : 4 key k-steps x 8 d n-tiles ----
        #pragma unroll
        for (int s = 0; s < 4; s++) {
            uint32_t ap0 = packh2(sacc[2 * s][0],     sacc[2 * s][1]);
            uint32_t ap1 = packh2(sacc[2 * s][2],     sacc[2 * s][3]);
            uint32_t ap2 = packh2(sacc[2 * s + 1][0], sacc[2 * s + 1][1]);
            uint32_t ap3 = packh2(sacc[2 * s + 1][2], sacc[2 * s + 1][3]);
            #pragma unroll
            for (int jj = 0; jj < 4; jj++) {
                uint32_t b0, b1, b2, b3;
                LDSM4T(b0, b1, b2, b3, vbase + s * (16 * FSTR * 2) + jj * 32);
                mma_f16(oacc[2 * jj],     ap0, ap1, ap2, ap3, b0, b1);
                mma_f16(oacc[2 * jj + 1], ap0, ap1, ap2, ap3, b2, b3);
            }
        }
        __syncthreads();
    }

    // ---- epilogue: x2 = x + O / l ----
    #pragma unroll
    for (int hf = 0; hf < 2; hf++) {
        float inv = 1.0f / lrun[hf];
        int row = q0 + wid * 16 + rq + hf * 8;
        size_t base = ((size_t)(b * N_ + row)) * C_ + h * D_;
        #pragma unroll
        for (int j = 0; j < 8; j++) {
            int c = j * 8 + 2 * cq;
            float2 xv = *(const float2*)(x + base + c);
            float2 o;
            o.x = oacc[j][2 * hf]     * inv + xv.x;
            o.y = oacc[j][2 * hf + 1] * inv + xv.y;
            *(float2*)(x2 + base + c) = o;
        }
    }
}

// ---------------- reductions ----------------
__device__ __forceinline__ float blockReduceSum(float v) {
    __shared__ float sh[8];
    int lane = threadIdx.x & 31, w = threadIdx.x >> 5;
    #pragma unroll
    for (int o = 16; o > 0; o >>= 1) v += __shfl_down_sync(0xffffffffu, v, o);
    if (lane == 0) sh[w] = v;
    __syncthreads();
    if (w == 0) {
        float t = (lane < 8) ? sh[lane] : 0.f;
        #pragma unroll
        for (int o = 4; o > 0; o >>= 1) t += __shfl_down_sync(0xffffffffu, t, o);
        if (lane == 0) sh[0] = t;
    }
    __syncthreads();
    float r = sh[0];
    __syncthreads();
    return r;
}

// ---------------- LayerNorm -> f16 ----------------
__global__ __launch_bounds__(256) void ln_kernel(const float* __restrict__ x,
                                                 const float* __restrict__ g,
                                                 const float* __restrict__ b,
                                                 __half* __restrict__ out) {
    size_t row = blockIdx.x;
    const float* xr = x + row * C_;
    int t = threadIdx.x;
    float a = xr[t], c = xr[t + 256];
    float s = blockReduceSum(a + c);
    float mu = s * (1.0f / C_);
    float da = a - mu, dc = c - mu;
    float vs = blockReduceSum(da * da + dc * dc);
    float rstd = rsqrtf(vs * (1.0f / C_) + EPS_);
    out[row * C_ + t]       = __float2half(da * rstd * g[t]       + b[t]);
    out[row * C_ + t + 256] = __float2half(dc * rstd * g[t + 256] + b[t + 256]);
}

// ---------------- q' combine (x0.125 folded) ----------------
__global__ __launch_bounds__(256) void qprime_kernel(const __half* __restrict__ qkv,
                                                     __half* __restrict__ qp) {
    int idx = blockIdx.x * 256 + threadIdx.x;
    int c = idx & (C_ - 1);
    int bn = idx >> 9;
    int n = bn % N_;
    float v = __half2float(qkv[(size_t)bn * (3 * C_) + c]);
    if (n >= 512)  v += 0.5f  * __half2float(qkv[(size_t)(bn - 512)  * (3 * C_) + c]);
    if (n >= 1024) v += 0.25f * __half2float(qkv[(size_t)(bn - 1024) * (3 * C_) + c]);
    qp[idx] = __float2half(0.125f * v);
}

// ---------------- f32 -> f16 convert ----------------
__global__ __launch_bounds__(256) void cvt_kernel(const float* __restrict__ in,
                                                  __half* __restrict__ out, int n) {
    int idx = blockIdx.x * 256 + threadIdx.x;
    if (idx * 4 < n) {
        float4 v = *(const float4*)(in + idx * 4);
        __half2 lo = __float22half2_rn(make_float2(v.x, v.y));
        __half2 hi = __float22half2_rn(make_float2(v.z, v.w));
        uint2 o; o.x = *(uint32_t*)&lo; o.y = *(uint32_t*)&hi;
        *(uint2*)(out + idx * 4) = o;
    }
}

// ---------------- launch ----------------
extern "C" void kernel_launch(void* const* d_in, const int* in_sizes, int n_in,
                              void* d_out, int out_size) {
    const float* x      = (const float*)d_in[0];
    const float* ln1_g  = (const float*)d_in[1];
    const float* ln1_b  = (const float*)d_in[2];
    const float* qkv_w  = (const float*)d_in[3];
    const float* qkv_b  = (const float*)d_in[4];
    const float* ln2_g  = (const float*)d_in[5];
    const float* ln2_b  = (const float*)d_in[6];
    const float* fc1_w  = (const float*)d_in[7];
    const float* fc1_b  = (const float*)d_in[8];
    const float* fc2_w  = (const float*)d_in[9];
    const float* fc2_b  = (const float*)d_in[10];
    float* out = (float*)d_out;

    __half *h, *qkv, *qp, *m1, *w1, *w2, *w3;
    float *x2;
    cudaGetSymbolAddress((void**)&h,   g_h);
    cudaGetSymbolAddress((void**)&qkv, g_qkv);
    cudaGetSymbolAddress((void**)&qp,  g_qp);
    cudaGetSymbolAddress((void**)&x2,  g_x2);
    cudaGetSymbolAddress((void**)&m1,  g_m1);
    cudaGetSymbolAddress((void**)&w1,  g_w1);
    cudaGetSymbolAddress((void**)&w2,  g_w2);
    cudaGetSymbolAddress((void**)&w3,  g_w3);

    // weight conversions
    cvt_kernel<<<(C_ * 3 * C_ / 4 + 255) / 256, 256>>>(qkv_w, w1, C_ * 3 * C_);
    cvt_kernel<<<(C_ * HID_ / 4 + 255) / 256, 256>>>(fc1_w, w2, C_ * HID_);
    cvt_kernel<<<(HID_ * C_ / 4 + 255) / 256, 256>>>(fc2_w, w3, HID_ * C_);

    // 1. LN1 -> h (f16)
    ln_kernel<<<BN_, 256>>>(x, ln1_g, ln1_b, h);
    // 2. qkv = h @ qkv_w + b   (f16 out)
    gemm_h<0><<<dim3(3 * C_ / 128, BN_ / 128), 256>>>(
        h, C_, w1, 3 * C_, qkv, 3 * C_, qkv_b, nullptr, C_);
    // 3. q' combine (scale folded)
    qprime_kernel<<<BN_ * C_ / 256, 256>>>(qkv, qp);
    // 4-6. fused attention: x2 = x + softmax(q'k^T) v
    flash_kernel<<<dim3(N_ / 128, BH_), 256>>>(qp, qkv, x, x2);
    // 7. LN2 -> h (f16)
    ln_kernel<<<BN_, 256>>>(x2, ln2_g, ln2_b, h);
    // 8. m1 = gelu(h @ fc1_w + b)  (f16 out)
    gemm_h<1><<<dim3(HID_ / 128, BN_ / 128), 256>>>(
        h, C_, w2, HID_, m1, HID_, fc1_b, nullptr, C_);
    // 9. out = x2 + m1 @ fc2_w + b  (f32 out)
    gemm_h<2><<<dim3(C_ / 128, BN_ / 128), 256>>>(
        m1, HID_, w3, C_, out, C_, fc2_b, x2, HID_);
}

// round 5
// speedup vs baseline: 7.5826x; 1.1239x over previous
#include <cuda_runtime.h>
#include <cuda_fp16.h>
#include <math.h>
#include <stdint.h>

#define B_   4
#define N_   1536
#define C_   512
#define H_   8
#define D_   64
#define HID_ 1024
#define BN_  (B_*N_)    // 6144
#define BH_  (B_*H_)    // 32
#define EPS_ 1e-5f
#define LOG2E 1.4426950408889634f
#define SOFF  14.0f     // log2-domain softmax offset (exact-ratio invariant)

// ---------------- scratch ----------------
__device__ __half g_h   [BN_*C_];
__device__ __half g_qkv [BN_*3*C_];
__device__ __half g_qp  [BN_*C_];
__device__ float  g_x2  [BN_*C_];
__device__ __half g_m1  [BN_*HID_];
__device__ __half g_w1  [C_*3*C_];
__device__ __half g_w2  [C_*HID_];
__device__ __half g_w3  [HID_*C_];

// ---------------- asm helpers ----------------
#define LDSM4(d0,d1,d2,d3,addr) \
    asm volatile("ldmatrix.sync.aligned.m8n8.x4.shared.b16 {%0,%1,%2,%3}, [%4];" \
        : "=r"(d0),"=r"(d1),"=r"(d2),"=r"(d3) : "r"(addr))
#define LDSM4T(d0,d1,d2,d3,addr) \
    asm volatile("ldmatrix.sync.aligned.m8n8.x4.trans.shared.b16 {%0,%1,%2,%3}, [%4];" \
        : "=r"(d0),"=r"(d1),"=r"(d2),"=r"(d3) : "r"(addr))

__device__ __forceinline__ void mma_f16(float c[4], uint32_t a0, uint32_t a1,
                                        uint32_t a2, uint32_t a3,
                                        uint32_t b0, uint32_t b1) {
    asm volatile(
        "mma.sync.aligned.m16n8k16.row.col.f32.f16.f16.f32 "
        "{%0,%1,%2,%3}, {%4,%5,%6,%7}, {%8,%9}, {%0,%1,%2,%3};"
        : "+f"(c[0]), "+f"(c[1]), "+f"(c[2]), "+f"(c[3])
        : "r"(a0), "r"(a1), "r"(a2), "r"(a3), "r"(b0), "r"(b1));
}
__device__ __forceinline__ uint32_t packh2(float lo, float hi) {
    __half2 h = __float22half2_rn(make_float2(lo, hi));
    return *(uint32_t*)&h;
}
__device__ __forceinline__ uint32_t smem_u32(const void* p) {
    return (uint32_t)__cvta_generic_to_shared(p);
}
__device__ __forceinline__ float ex2f(float x) {
    float y; asm("ex2.approx.f32 %0, %1;" : "=f"(y) : "f"(x)); return y;
}
__device__ __forceinline__ void cp16(uint32_t dst, const void* src) {
    asm volatile("cp.async.cg.shared.global [%0], [%1], 16;" :: "r"(dst), "l"(src));
}
#define CP_COMMIT() asm volatile("cp.async.commit_group;" ::: "memory")
#define CP_WAIT(n)  asm volatile("cp.async.wait_group %0;" :: "n"(n) : "memory")

// ================= dense fp16 GEMM: C = epi(A @ B + bias) =================
// A f16 [M,K] rm, B f16 [K,N] rm. 128x128 tile, kt=32, 8 warps (4m x 2n).
// EPI: 0 -> f16 out (+bias) | 1 -> f16 out gelu(+bias) | 2 -> f32 out (+bias+resid)
#define ASTR 40    // halves per A smem row (80B, 16B-aligned rows)
#define BSTR 136   // halves per B smem row (272B)
template<int EPI>
__global__ __launch_bounds__(256) void gemm_h(
    const __half* __restrict__ A, int lda,
    const __half* __restrict__ Bw, int ldb,
    void* __restrict__ Cout, int ldc,
    const float* __restrict__ bias,
    const float* __restrict__ resid, int K)
{
    __shared__ __align__(16) __half As[2][128 * ASTR];
    __shared__ __align__(16) __half Bs[2][32 * BSTR];

    int tid = threadIdx.x, wid = tid >> 5, lane = tid & 31;
    int wm = wid & 3, wn = wid >> 2;
    int m0 = blockIdx.y * 128, n0 = blockIdx.x * 128;

    float acc[2][8][4];
    #pragma unroll
    for (int i = 0; i < 2; i++)
        #pragma unroll
        for (int j = 0; j < 8; j++)
            #pragma unroll
            for (int q = 0; q < 4; q++) acc[i][j][q] = 0.f;

    int ar = (tid >> 2), ac = (tid & 3);
    int bk = (tid >> 4), bc = (tid & 15);
    const __half* Ag = A + (size_t)(m0 + ar) * lda + ac * 8;
    const __half* Bg = Bw + (size_t)bk * ldb + n0 + bc * 8;

    uint32_t dA0[2], dA1[2], dB0[2], dB1[2];
    #pragma unroll
    for (int s = 0; s < 2; s++) {
        dA0[s] = smem_u32(&As[s][ar * ASTR + ac * 8]);
        dA1[s] = smem_u32(&As[s][(ar + 64) * ASTR + ac * 8]);
        dB0[s] = smem_u32(&Bs[s][bk * BSTR + bc * 8]);
        dB1[s] = smem_u32(&Bs[s][(bk + 16) * BSTR + bc * 8]);
    }
    int T = K >> 5;
    // prologue: stage 0, 1
    {
        cp16(dA0[0], Ag);  cp16(dA1[0], Ag + (size_t)64 * lda);
        cp16(dB0[0], Bg);  cp16(dB1[0], Bg + (size_t)16 * ldb);
        CP_COMMIT();
        cp16(dA0[1], Ag + 32);  cp16(dA1[1], Ag + (size_t)64 * lda + 32);
        cp16(dB0[1], Bg + (size_t)32 * ldb);  cp16(dB1[1], Bg + (size_t)48 * ldb);
        CP_COMMIT();
    }

    int l15 = lane & 15, lhi = lane >> 4;
    for (int kt = 0; kt < T; kt++) {
        int buf = kt & 1;
        if (kt < T - 1) CP_WAIT(1); else CP_WAIT(0);
        __syncthreads();

        uint32_t sA = smem_u32(&As[buf][0]);
        uint32_t sB = smem_u32(&Bs[buf][0]);
        uint32_t af[2][2][4];
        #pragma unroll
        for (int i = 0; i < 2; i++) {
            uint32_t base = sA + ((wm * 32 + i * 16 + l15) * ASTR + lhi * 8) * 2;
            #pragma unroll
            for (int s = 0; s < 2; s++)
                LDSM4(af[i][s][0], af[i][s][1], af[i][s][2], af[i][s][3],
                      base + s * 32);
        }
        #pragma unroll
        for (int s = 0; s < 2; s++) {
            uint32_t bbase = sB + ((s * 16 + l15) * BSTR + wn * 64 + lhi * 8) * 2;
            #pragma unroll
            for (int jj = 0; jj < 4; jj++) {
                uint32_t b0, b1, b2, b3;
                LDSM4T(b0, b1, b2, b3, bbase + jj * 32);
                #pragma unroll
                for (int i = 0; i < 2; i++) {
                    mma_f16(acc[i][2 * jj],     af[i][s][0], af[i][s][1], af[i][s][2], af[i][s][3], b0, b1);
                    mma_f16(acc[i][2 * jj + 1], af[i][s][0], af[i][s][1], af[i][s][2], af[i][s][3], b2, b3);
                }
            }
        }
        __syncthreads();
        if (kt + 2 < T) {
            const __half* Ag2 = Ag + (kt + 2) * 32;
            const __half* Bg2 = Bg + (size_t)(kt + 2) * 32 * ldb;
            cp16(dA0[buf], Ag2);  cp16(dA1[buf], Ag2 + (size_t)64 * lda);
            cp16(dB0[buf], Bg2);  cp16(dB1[buf], Bg2 + (size_t)16 * ldb);
            CP_COMMIT();
        }
    }

    // epilogue
    int rq = lane >> 2, cq = lane & 3;
    #pragma unroll
    for (int i = 0; i < 2; i++) {
        #pragma unroll
        for (int half = 0; half < 2; half++) {
            size_t r = (size_t)(m0 + wm * 32 + i * 16 + rq + half * 8);
            #pragma unroll
            for (int j = 0; j < 8; j++) {
                int c = n0 + wn * 64 + j * 8 + 2 * cq;
                float v0 = acc[i][j][half * 2 + 0];
                float v1 = acc[i][j][half * 2 + 1];
                if (EPI == 0) {
                    v0 += bias[c]; v1 += bias[c + 1];
                    *(uint32_t*)((__half*)Cout + r * ldc + c) = packh2(v0, v1);
                } else if (EPI == 1) {
                    v0 += bias[c]; v1 += bias[c + 1];
                    v0 = 0.5f * v0 * (1.0f + erff(v0 * 0.70710678118654752f));
                    v1 = 0.5f * v1 * (1.0f + erff(v1 * 0.70710678118654752f));
                    *(uint32_t*)((__half*)Cout + r * ldc + c) = packh2(v0, v1);
                } else {
                    const float* rr = resid + r * ldc;
                    float2 o;
                    o.x = v0 + bias[c]     + rr[c];
                    o.y = v1 + bias[c + 1] + rr[c + 1];
                    *(float2*)((float*)Cout + r * ldc + c) = o;
                }
            }
        }
    }
}

// ================= fused flash attention (log2-domain, fixed offset) =================
// x2 = x + softmax(q' k^T) v ; scale*log2e folded into q', offset -SOFF in acc init.
#define FSTR 72   // halves per smem row (144B)
__global__ __launch_bounds__(256) void flash_kernel(
    const __half* __restrict__ qp, const __half* __restrict__ qkv,
    const float* __restrict__ x, float* __restrict__ x2)
{
    // S[buf][tens][64*FSTR]; Q tile temporarily occupies S[0] (exactly 128*FSTR)
    __shared__ __align__(16) __half S[2][2][64 * FSTR];

    int tid = threadIdx.x, wid = tid >> 5, lane = tid & 31;
    int bh = blockIdx.y, b = bh >> 3, h = bh & 7;
    int q0 = blockIdx.x * 128;
    int l15 = lane & 15, lhi = lane >> 4;
    int rq = lane >> 2, cq = lane & 3;

    // ---- load Q tile into S[0] via cp.async ----
    {
        int row = tid >> 3, c = tid & 7;
        __half* Qs = &S[0][0][0];
        #pragma unroll
        for (int it = 0; it < 4; it++) {
            int r = row + it * 32;
            cp16(smem_u32(&Qs[r * FSTR + c * 8]),
                 qp + ((size_t)(b * N_ + q0 + r)) * C_ + h * D_ + c * 8);
        }
        CP_COMMIT();
        CP_WAIT(0);
    }
    __syncthreads();

    uint32_t aq[4][4];
    {
        uint32_t base = smem_u32(&S[0][0][0]) + ((wid * 16 + l15) * FSTR + lhi * 8) * 2;
        #pragma unroll
        for (int s = 0; s < 4; s++)
            LDSM4(aq[s][0], aq[s][1], aq[s][2], aq[s][3], base + s * 32);
    }
    __syncthreads();   // all warps done reading Q region

    float oacc[8][4];
    #pragma unroll
    for (int j = 0; j < 8; j++)
        #pragma unroll
        for (int q = 0; q < 4; q++) oacc[j][q] = 0.f;
    float lsum0 = 0.f, lsum1 = 0.f;

    // KV cp.async fill: 4x16B per thread per chunk
    const __half* qkvb = qkv + (size_t)(b * N_) * (3 * C_) + h * D_;
    int frow = (tid >> 3) & 63;   // with tens = idx>>9
    int fc = tid & 7;

    #define KV_ISSUE(kc_, buf_) do {                                          \
        int _kb = (kc_) * 64;                                                 \
        _Pragma("unroll")                                                     \
        for (int it = 0; it < 4; it++) {                                      \
            int idx = tid + it * 256;                                         \
            int tens = idx >> 9;                                              \
            int row = (idx >> 3) & 63;                                        \
            int c = idx & 7;                                                  \
            cp16(smem_u32(&S[buf_][tens][row * FSTR + c * 8]),                \
                 qkvb + (size_t)(_kb + row) * (3 * C_)                        \
                      + (tens ? 2 * C_ : C_) + c * 8);                        \
        }                                                                     \
        CP_COMMIT();                                                          \
    } while (0)

    KV_ISSUE(0, 0);
    KV_ISSUE(1, 1);

    for (int kc = 0; kc < 24; kc++) {
        int buf = kc & 1;
        if (kc < 23) CP_WAIT(1); else CP_WAIT(0);
        __syncthreads();

        uint32_t kbase = smem_u32(&S[buf][0][0])
            + ((((lane >> 4) & 1) * 8 + (lane & 7)) * FSTR + ((lane >> 3) & 1) * 8) * 2;
        uint32_t vbase = smem_u32(&S[buf][1][0]) + (l15 * FSTR + lhi * 8) * 2;

        // ---- S = Q K^T (log2 domain, offset -SOFF) ----
        float sacc[8][4];
        #pragma unroll
        for (int j = 0; j < 8; j++)
            #pragma unroll
            for (int q = 0; q < 4; q++) sacc[j][q] = -SOFF;
        #pragma unroll
        for (int s = 0; s < 4; s++) {
            #pragma unroll
            for (int jj = 0; jj < 4; jj++) {
                uint32_t b0, b1, b2, b3;
                LDSM4(b0, b1, b2, b3, kbase + jj * (16 * FSTR * 2) + s * 32);
                mma_f16(sacc[2 * jj],     aq[s][0], aq[s][1], aq[s][2], aq[s][3], b0, b1);
                mma_f16(sacc[2 * jj + 1], aq[s][0], aq[s][1], aq[s][2], aq[s][3], b2, b3);
            }
        }

        // ---- p = 2^s ; accumulate l; pack for PV ----
        uint32_t ph[8][2];
        #pragma unroll
        for (int j = 0; j < 8; j++) {
            float p0 = ex2f(sacc[j][0]);
            float p1 = ex2f(sacc[j][1]);
            float p2 = ex2f(sacc[j][2]);
            float p3 = ex2f(sacc[j][3]);
            lsum0 += p0 + p1;
            lsum1 += p2 + p3;
            ph[j][0] = packh2(p0, p1);
            ph[j][1] = packh2(p2, p3);
        }

        // ---- O += P V ----
        #pragma unroll
        for (int s = 0; s < 4; s++) {
            #pragma unroll
            for (int jj = 0; jj < 4; jj++) {
                uint32_t b0, b1, b2, b3;
                LDSM4T(b0, b1, b2, b3, vbase + s * (16 * FSTR * 2) + jj * 32);
                mma_f16(oacc[2 * jj],     ph[2 * s][0], ph[2 * s][1], ph[2 * s + 1][0], ph[2 * s + 1][1], b0, b1);
                mma_f16(oacc[2 * jj + 1], ph[2 * s][0], ph[2 * s][1], ph[2 * s + 1][0], ph[2 * s + 1][1], b2, b3);
            }
        }
        __syncthreads();
        if (kc + 2 < 24) KV_ISSUE(kc + 2, buf);
    }

    // ---- final l reduction (cq group of 4 threads shares each row) ----
    lsum0 += __shfl_xor_sync(0xffffffffu, lsum0, 1);
    lsum0 += __shfl_xor_sync(0xffffffffu, lsum0, 2);
    lsum1 += __shfl_xor_sync(0xffffffffu, lsum1, 1);
    lsum1 += __shfl_xor_sync(0xffffffffu, lsum1, 2);
    float inv[2] = {1.0f / lsum0, 1.0f / lsum1};

    #pragma unroll
    for (int hf = 0; hf < 2; hf++) {
        int row = q0 + wid * 16 + rq + hf * 8;
        size_t base = ((size_t)(b * N_ + row)) * C_ + h * D_;
        #pragma unroll
        for (int j = 0; j < 8; j++) {
            int c = j * 8 + 2 * cq;
            float2 xv = *(const float2*)(x + base + c);
            float2 o;
            o.x = oacc[j][2 * hf]     * inv[hf] + xv.x;
            o.y = oacc[j][2 * hf + 1] * inv[hf] + xv.y;
            *(float2*)(x2 + base + c) = o;
        }
    }
}

// ---------------- reductions ----------------
__device__ __forceinline__ float blockReduceSum(float v) {
    __shared__ float sh[8];
    int lane = threadIdx.x & 31, w = threadIdx.x >> 5;
    #pragma unroll
    for (int o = 16; o > 0; o >>= 1) v += __shfl_down_sync(0xffffffffu, v, o);
    if (lane == 0) sh[w] = v;
    __syncthreads();
    if (w == 0) {
        float t = (lane < 8) ? sh[lane] : 0.f;
        #pragma unroll
        for (int o = 4; o > 0; o >>= 1) t += __shfl_down_sync(0xffffffffu, t, o);
        if (lane == 0) sh[0] = t;
    }
    __syncthreads();
    float r = sh[0];
    __syncthreads();
    return r;
}

// ---------------- LayerNorm -> f16 ----------------
__global__ __launch_bounds__(256) void ln_kernel(const float* __restrict__ x,
                                                 const float* __restrict__ g,
                                                 const float* __restrict__ b,
                                                 __half* __restrict__ out) {
    size_t row = blockIdx.x;
    const float* xr = x + row * C_;
    int t = threadIdx.x;
    float a = xr[t], c = xr[t + 256];
    float s = blockReduceSum(a + c);
    float mu = s * (1.0f / C_);
    float da = a - mu, dc = c - mu;
    float vs = blockReduceSum(da * da + dc * dc);
    float rstd = rsqrtf(vs * (1.0f / C_) + EPS_);
    out[row * C_ + t]       = __float2half(da * rstd * g[t]       + b[t]);
    out[row * C_ + t + 256] = __float2half(dc * rstd * g[t + 256] + b[t + 256]);
}

// ---------------- q' combine, scaled by 0.125*log2e, vectorized ----------------
__global__ __launch_bounds__(256) void qprime_kernel(const __half* __restrict__ qkv,
                                                     __half* __restrict__ qp) {
    int idx = (blockIdx.x * 256 + threadIdx.x);            // over BN_*C_/8
    int c8 = (idx & 63) * 8;                               // C_/8 = 64
    int bn = idx >> 6;
    int n = bn % N_;
    const float ksc = 0.125f * LOG2E;

    uint4 va = *(const uint4*)(qkv + (size_t)bn * (3 * C_) + c8);
    __half2* ha = (__half2*)&va;
    float2 f[4];
    #pragma unroll
    for (int i = 0; i < 4; i++) f[i] = __half22float2(ha[i]);
    if (n >= 512) {
        uint4 vb = *(const uint4*)(qkv + (size_t)(bn - 512) * (3 * C_) + c8);
        __half2* hb = (__half2*)&vb;
        #pragma unroll
        for (int i = 0; i < 4; i++) {
            float2 g2 = __half22float2(hb[i]);
            f[i].x += 0.5f * g2.x; f[i].y += 0.5f * g2.y;
        }
    }
    if (n >= 1024) {
        uint4 vc = *(const uint4*)(qkv + (size_t)(bn - 1024) * (3 * C_) + c8);
        __half2* hc = (__half2*)&vc;
        #pragma unroll
        for (int i = 0; i < 4; i++) {
            float2 g2 = __half22float2(hc[i]);
            f[i].x += 0.25f * g2.x; f[i].y += 0.25f * g2.y;
        }
    }
    uint4 o;
    uint32_t* op = (uint32_t*)&o;
    #pragma unroll
    for (int i = 0; i < 4; i++) op[i] = packh2(f[i].x * ksc, f[i].y * ksc);
    *(uint4*)(qp + (size_t)bn * C_ + c8) = o;
}

// ---------------- f32 -> f16 convert ----------------
__global__ __launch_bounds__(256) void cvt_kernel(const float* __restrict__ in,
                                                  __half* __restrict__ out, int n) {
    int idx = blockIdx.x * 256 + threadIdx.x;
    if (idx * 4 < n) {
        float4 v = *(const float4*)(in + idx * 4);
        __half2 lo = __float22half2_rn(make_float2(v.x, v.y));
        __half2 hi = __float22half2_rn(make_float2(v.z, v.w));
        uint2 o; o.x = *(uint32_t*)&lo; o.y = *(uint32_t*)&hi;
        *(uint2*)(out + idx * 4) = o;
    }
}

// ---------------- launch ----------------
extern "C" void kernel_launch(void* const* d_in, const int* in_sizes, int n_in,
                              void* d_out, int out_size) {
    const float* x      = (const float*)d_in[0];
    const float* ln1_g  = (const float*)d_in[1];
    const float* ln1_b  = (const float*)d_in[2];
    const float* qkv_w  = (const float*)d_in[3];
    const float* qkv_b  = (const float*)d_in[4];
    const float* ln2_g  = (const float*)d_in[5];
    const float* ln2_b  = (const float*)d_in[6];
    const float* fc1_w  = (const float*)d_in[7];
    const float* fc1_b  = (const float*)d_in[8];
    const float* fc2_w  = (const float*)d_in[9];
    const float* fc2_b  = (const float*)d_in[10];
    float* out = (float*)d_out;

    __half *h, *qkv, *qp, *m1, *w1, *w2, *w3;
    float *x2;
    cudaGetSymbolAddress((void**)&h,   g_h);
    cudaGetSymbolAddress((void**)&qkv, g_qkv);
    cudaGetSymbolAddress((void**)&qp,  g_qp);
    cudaGetSymbolAddress((void**)&x2,  g_x2);
    cudaGetSymbolAddress((void**)&m1,  g_m1);
    cudaGetSymbolAddress((void**)&w1,  g_w1);
    cudaGetSymbolAddress((void**)&w2,  g_w2);
    cudaGetSymbolAddress((void**)&w3,  g_w3);

    cvt_kernel<<<(C_ * 3 * C_ / 4 + 255) / 256, 256>>>(qkv_w, w1, C_ * 3 * C_);
    cvt_kernel<<<(C_ * HID_ / 4 + 255) / 256, 256>>>(fc1_w, w2, C_ * HID_);
    cvt_kernel<<<(HID_ * C_ / 4 + 255) / 256, 256>>>(fc2_w, w3, HID_ * C_);

    // 1. LN1 -> h (f16)
    ln_kernel<<<BN_, 256>>>(x, ln1_g, ln1_b, h);
    // 2. qkv = h @ qkv_w + b   (f16 out)
    gemm_h<0><<<dim3(3 * C_ / 128, BN_ / 128), 256>>>(
        h, C_, w1, 3 * C_, qkv, 3 * C_, qkv_b, nullptr, C_);
    // 3. q' combine (scale*log2e folded)
    qprime_kernel<<<BN_ * C_ / 8 / 256, 256>>>(qkv, qp);
    // 4-6. fused attention
    flash_kernel<<<dim3(N_ / 128, BH_), 256>>>(qp, qkv, x, x2);
    // 7. LN2 -> h (f16)
    ln_kernel<<<BN_, 256>>>(x2, ln2_g, ln2_b, h);
    // 8. m1 = gelu(h @ fc1_w + b)
    gemm_h<1><<<dim3(HID_ / 128, BN_ / 128), 256>>>(
        h, C_, w2, HID_, m1, HID_, fc1_b, nullptr, C_);
    // 9. out = x2 + m1 @ fc2_w + b
    gemm_h<2><<<dim3(C_ / 128, BN_ / 128), 256>>>(
        m1, HID_, w3, C_, out, C_, fc2_b, x2, HID_);
}

// round 6
// speedup vs baseline: 8.0860x; 1.0664x over previous
#include <cuda_runtime.h>
#include <cuda_fp16.h>
#include <math.h>
#include <stdint.h>

#define B_   4
#define N_   1536
#define C_   512
#define H_   8
#define D_   64
#define HID_ 1024
#define BN_  (B_*N_)    // 6144
#define BH_  (B_*H_)    // 32
#define EPS_ 1e-5f
#define LOG2E 1.4426950408889634f
#define SOFF  14.0f     // log2-domain softmax offset

// ---------------- scratch ----------------
__device__ __half g_h   [BN_*C_];
__device__ __half g_qkv [BN_*3*C_];
__device__ float  g_x2  [BN_*C_];
__device__ __half g_m1  [BN_*HID_];
__device__ __half g_w1  [C_*3*C_];
__device__ __half g_w2  [C_*HID_];
__device__ __half g_w3  [HID_*C_];

// ---------------- asm helpers ----------------
#define LDSM4(d0,d1,d2,d3,addr) \
    asm volatile("ldmatrix.sync.aligned.m8n8.x4.shared.b16 {%0,%1,%2,%3}, [%4];" \
        : "=r"(d0),"=r"(d1),"=r"(d2),"=r"(d3) : "r"(addr))
#define LDSM4T(d0,d1,d2,d3,addr) \
    asm volatile("ldmatrix.sync.aligned.m8n8.x4.trans.shared.b16 {%0,%1,%2,%3}, [%4];" \
        : "=r"(d0),"=r"(d1),"=r"(d2),"=r"(d3) : "r"(addr))

__device__ __forceinline__ void mma_f16(float c[4], uint32_t a0, uint32_t a1,
                                        uint32_t a2, uint32_t a3,
                                        uint32_t b0, uint32_t b1) {
    asm volatile(
        "mma.sync.aligned.m16n8k16.row.col.f32.f16.f16.f32 "
        "{%0,%1,%2,%3}, {%4,%5,%6,%7}, {%8,%9}, {%0,%1,%2,%3};"
        : "+f"(c[0]), "+f"(c[1]), "+f"(c[2]), "+f"(c[3])
        : "r"(a0), "r"(a1), "r"(a2), "r"(a3), "r"(b0), "r"(b1));
}
__device__ __forceinline__ uint32_t packh2(float lo, float hi) {
    __half2 h = __float22half2_rn(make_float2(lo, hi));
    return *(uint32_t*)&h;
}
__device__ __forceinline__ uint32_t smem_u32(const void* p) {
    return (uint32_t)__cvta_generic_to_shared(p);
}
__device__ __forceinline__ float ex2f(float x) {
    float y; asm("ex2.approx.f32 %0, %1;" : "=f"(y) : "f"(x)); return y;
}
__device__ __forceinline__ void cp16(uint32_t dst, const void* src) {
    asm volatile("cp.async.cg.shared.global [%0], [%1], 16;" :: "r"(dst), "l"(src));
}
#define CP_COMMIT() asm volatile("cp.async.commit_group;" ::: "memory")
#define CP_WAIT(n)  asm volatile("cp.async.wait_group %0;" :: "n"(n) : "memory")

// ================= dense fp16 GEMM: C = epi(A @ B + bias) =================
#define ASTR 40
#define BSTR 136
template<int EPI>
__global__ __launch_bounds__(256) void gemm_h(
    const __half* __restrict__ A, int lda,
    const __half* __restrict__ Bw, int ldb,
    void* __restrict__ Cout, int ldc,
    const float* __restrict__ bias,
    const float* __restrict__ resid, int K)
{
    __shared__ __align__(16) __half As[2][128 * ASTR];
    __shared__ __align__(16) __half Bs[2][32 * BSTR];

    int tid = threadIdx.x, wid = tid >> 5, lane = tid & 31;
    int wm = wid & 3, wn = wid >> 2;
    int m0 = blockIdx.y * 128, n0 = blockIdx.x * 128;

    float acc[2][8][4];
    #pragma unroll
    for (int i = 0; i < 2; i++)
        #pragma unroll
        for (int j = 0; j < 8; j++)
            #pragma unroll
            for (int q = 0; q < 4; q++) acc[i][j][q] = 0.f;

    int ar = (tid >> 2), ac = (tid & 3);
    int bk = (tid >> 4), bc = (tid & 15);
    const __half* Ag = A + (size_t)(m0 + ar) * lda + ac * 8;
    const __half* Bg = Bw + (size_t)bk * ldb + n0 + bc * 8;

    uint32_t dA0[2], dA1[2], dB0[2], dB1[2];
    #pragma unroll
    for (int s = 0; s < 2; s++) {
        dA0[s] = smem_u32(&As[s][ar * ASTR + ac * 8]);
        dA1[s] = smem_u32(&As[s][(ar + 64) * ASTR + ac * 8]);
        dB0[s] = smem_u32(&Bs[s][bk * BSTR + bc * 8]);
        dB1[s] = smem_u32(&Bs[s][(bk + 16) * BSTR + bc * 8]);
    }
    int T = K >> 5;
    {
        cp16(dA0[0], Ag);  cp16(dA1[0], Ag + (size_t)64 * lda);
        cp16(dB0[0], Bg);  cp16(dB1[0], Bg + (size_t)16 * ldb);
        CP_COMMIT();
        cp16(dA0[1], Ag + 32);  cp16(dA1[1], Ag + (size_t)64 * lda + 32);
        cp16(dB0[1], Bg + (size_t)32 * ldb);  cp16(dB1[1], Bg + (size_t)48 * ldb);
        CP_COMMIT();
    }

    int l15 = lane & 15, lhi = lane >> 4;
    for (int kt = 0; kt < T; kt++) {
        int buf = kt & 1;
        if (kt < T - 1) CP_WAIT(1); else CP_WAIT(0);
        __syncthreads();

        uint32_t sA = smem_u32(&As[buf][0]);
        uint32_t sB = smem_u32(&Bs[buf][0]);
        uint32_t af[2][2][4];
        #pragma unroll
        for (int i = 0; i < 2; i++) {
            uint32_t base = sA + ((wm * 32 + i * 16 + l15) * ASTR + lhi * 8) * 2;
            #pragma unroll
            for (int s = 0; s < 2; s++)
                LDSM4(af[i][s][0], af[i][s][1], af[i][s][2], af[i][s][3],
                      base + s * 32);
        }
        #pragma unroll
        for (int s = 0; s < 2; s++) {
            uint32_t bbase = sB + ((s * 16 + l15) * BSTR + wn * 64 + lhi * 8) * 2;
            #pragma unroll
            for (int jj = 0; jj < 4; jj++) {
                uint32_t b0, b1, b2, b3;
                LDSM4T(b0, b1, b2, b3, bbase + jj * 32);
                #pragma unroll
                for (int i = 0; i < 2; i++) {
                    mma_f16(acc[i][2 * jj],     af[i][s][0], af[i][s][1], af[i][s][2], af[i][s][3], b0, b1);
                    mma_f16(acc[i][2 * jj + 1], af[i][s][0], af[i][s][1], af[i][s][2], af[i][s][3], b2, b3);
                }
            }
        }
        __syncthreads();
        if (kt + 2 < T) {
            const __half* Ag2 = Ag + (kt + 2) * 32;
            const __half* Bg2 = Bg + (size_t)(kt + 2) * 32 * ldb;
            cp16(dA0[buf], Ag2);  cp16(dA1[buf], Ag2 + (size_t)64 * lda);
            cp16(dB0[buf], Bg2);  cp16(dB1[buf], Bg2 + (size_t)16 * ldb);
            CP_COMMIT();
        }
    }

    int rq = lane >> 2, cq = lane & 3;
    #pragma unroll
    for (int i = 0; i < 2; i++) {
        #pragma unroll
        for (int half = 0; half < 2; half++) {
            size_t r = (size_t)(m0 + wm * 32 + i * 16 + rq + half * 8);
            #pragma unroll
            for (int j = 0; j < 8; j++) {
                int c = n0 + wn * 64 + j * 8 + 2 * cq;
                float v0 = acc[i][j][half * 2 + 0];
                float v1 = acc[i][j][half * 2 + 1];
                if (EPI == 0) {
                    v0 += bias[c]; v1 += bias[c + 1];
                    *(uint32_t*)((__half*)Cout + r * ldc + c) = packh2(v0, v1);
                } else if (EPI == 1) {
                    v0 += bias[c]; v1 += bias[c + 1];
                    v0 = 0.5f * v0 * (1.0f + erff(v0 * 0.70710678118654752f));
                    v1 = 0.5f * v1 * (1.0f + erff(v1 * 0.70710678118654752f));
                    *(uint32_t*)((__half*)Cout + r * ldc + c) = packh2(v0, v1);
                } else {
                    const float* rr = resid + r * ldc;
                    float2 o;
                    o.x = v0 + bias[c]     + rr[c];
                    o.y = v1 + bias[c + 1] + rr[c + 1];
                    *(float2*)((float*)Cout + r * ldc + c) = o;
                }
            }
        }
    }
}

// ================= fused flash attention (q' combine inlined) =================
// x2 = x + softmax(q' k^T) v ; q'[n] = (q[n]+.5q[n-512]+.25q[n-1024])*0.125*log2e
#define FSTR 72
struct __align__(16) FlashSmem {
    union {
        __half q[128 * FSTR];          // prologue only (9216 halves)
        __half kv[2][2][32 * FSTR];    // [buf][K/V][row] (9216 halves)
    };
};
__global__ __launch_bounds__(256, 2) void flash_kernel(
    const __half* __restrict__ qkv,
    const float* __restrict__ x, float* __restrict__ x2)
{
    __shared__ FlashSmem fs;

    int tid = threadIdx.x, wid = tid >> 5, lane = tid & 31;
    int bh = blockIdx.y, b = bh >> 3, h = bh & 7;
    int q0 = blockIdx.x * 128;
    int seg = blockIdx.x >> 2;          // 0,1,2 (uniform per block)
    int l15 = lane & 15, lhi = lane >> 4;
    int rq = lane >> 2, cq = lane & 3;
    const float ksc = 0.125f * LOG2E;

    // ---- Q prologue: load + segment combine + scale -> smem ----
    {
        const __half* qbase = qkv + ((size_t)(b * N_ + q0)) * (3 * C_) + h * D_;
        #pragma unroll
        for (int it = 0; it < 4; it++) {
            int idx = tid + it * 256;
            int row = idx >> 3, c8 = (idx & 7) * 8;
            const __half* p0 = qbase + (size_t)row * (3 * C_) + c8;
            uint4 va = *(const uint4*)p0;
            __half2* ha = (__half2*)&va;
            float2 f[4];
            #pragma unroll
            for (int i = 0; i < 4; i++) f[i] = __half22float2(ha[i]);
            if (seg >= 1) {
                uint4 vb = *(const uint4*)(p0 - (size_t)512 * (3 * C_));
                __half2* hb = (__half2*)&vb;
                #pragma unroll
                for (int i = 0; i < 4; i++) {
                    float2 g2 = __half22float2(hb[i]);
                    f[i].x += 0.5f * g2.x; f[i].y += 0.5f * g2.y;
                }
            }
            if (seg >= 2) {
                uint4 vc = *(const uint4*)(p0 - (size_t)1024 * (3 * C_));
                __half2* hc = (__half2*)&vc;
                #pragma unroll
                for (int i = 0; i < 4; i++) {
                    float2 g2 = __half22float2(hc[i]);
                    f[i].x += 0.25f * g2.x; f[i].y += 0.25f * g2.y;
                }
            }
            uint4 o; uint32_t* op = (uint32_t*)&o;
            #pragma unroll
            for (int i = 0; i < 4; i++) op[i] = packh2(f[i].x * ksc, f[i].y * ksc);
            *(uint4*)&fs.q[row * FSTR + c8] = o;
        }
    }
    __syncthreads();

    uint32_t aq[4][4];
    {
        uint32_t base = smem_u32(&fs.q[0]) + ((wid * 16 + l15) * FSTR + lhi * 8) * 2;
        #pragma unroll
        for (int s = 0; s < 4; s++)
            LDSM4(aq[s][0], aq[s][1], aq[s][2], aq[s][3], base + s * 32);
    }
    __syncthreads();   // Q region free for KV reuse

    float oacc[8][4];
    #pragma unroll
    for (int j = 0; j < 8; j++)
        #pragma unroll
        for (int q = 0; q < 4; q++) oacc[j][q] = 0.f;
    float lsum0 = 0.f, lsum1 = 0.f;

    const __half* qkvb = qkv + (size_t)(b * N_) * (3 * C_) + h * D_;

    #define KV_ISSUE(kc_, buf_) do {                                          \
        int _kb = (kc_) * 32;                                                 \
        _Pragma("unroll")                                                     \
        for (int it = 0; it < 2; it++) {                                      \
            int idx = tid + it * 256;                                         \
            int tens = idx >> 8;                                              \
            int row = (idx >> 3) & 31;                                        \
            int c = idx & 7;                                                  \
            cp16(smem_u32(&fs.kv[buf_][tens][row * FSTR + c * 8]),            \
                 qkvb + (size_t)(_kb + row) * (3 * C_)                        \
                      + (tens ? 2 * C_ : C_) + c * 8);                        \
        }                                                                     \
        CP_COMMIT();                                                          \
    } while (0)

    KV_ISSUE(0, 0);
    KV_ISSUE(1, 1);

    for (int kc = 0; kc < 48; kc++) {
        int buf = kc & 1;
        if (kc < 47) CP_WAIT(1); else CP_WAIT(0);
        __syncthreads();

        uint32_t kbase = smem_u32(&fs.kv[buf][0][0])
            + ((((lane >> 4) & 1) * 8 + (lane & 7)) * FSTR + ((lane >> 3) & 1) * 8) * 2;
        uint32_t vbase = smem_u32(&fs.kv[buf][1][0]) + (l15 * FSTR + lhi * 8) * 2;

        // ---- S = Q K^T (log2 domain, offset -SOFF) ----
        float sacc[4][4];
        #pragma unroll
        for (int j = 0; j < 4; j++)
            #pragma unroll
            for (int q = 0; q < 4; q++) sacc[j][q] = -SOFF;
        #pragma unroll
        for (int s = 0; s < 4; s++) {
            #pragma unroll
            for (int jj = 0; jj < 2; jj++) {
                uint32_t b0, b1, b2, b3;
                LDSM4(b0, b1, b2, b3, kbase + jj * (16 * FSTR * 2) + s * 32);
                mma_f16(sacc[2 * jj],     aq[s][0], aq[s][1], aq[s][2], aq[s][3], b0, b1);
                mma_f16(sacc[2 * jj + 1], aq[s][0], aq[s][1], aq[s][2], aq[s][3], b2, b3);
            }
        }

        // ---- p = 2^s ----
        uint32_t ph[4][2];
        #pragma unroll
        for (int j = 0; j < 4; j++) {
            float p0 = ex2f(sacc[j][0]);
            float p1 = ex2f(sacc[j][1]);
            float p2 = ex2f(sacc[j][2]);
            float p3 = ex2f(sacc[j][3]);
            lsum0 += p0 + p1;
            lsum1 += p2 + p3;
            ph[j][0] = packh2(p0, p1);
            ph[j][1] = packh2(p2, p3);
        }

        // ---- O += P V ----
        #pragma unroll
        for (int s = 0; s < 2; s++) {
            #pragma unroll
            for (int jj = 0; jj < 4; jj++) {
                uint32_t b0, b1, b2, b3;
                LDSM4T(b0, b1, b2, b3, vbase + s * (16 * FSTR * 2) + jj * 32);
                mma_f16(oacc[2 * jj],     ph[2 * s][0], ph[2 * s][1], ph[2 * s + 1][0], ph[2 * s + 1][1], b0, b1);
                mma_f16(oacc[2 * jj + 1], ph[2 * s][0], ph[2 * s][1], ph[2 * s + 1][0], ph[2 * s + 1][1], b2, b3);
            }
        }
        __syncthreads();
        if (kc + 2 < 48) KV_ISSUE(kc + 2, buf);
    }

    lsum0 += __shfl_xor_sync(0xffffffffu, lsum0, 1);
    lsum0 += __shfl_xor_sync(0xffffffffu, lsum0, 2);
    lsum1 += __shfl_xor_sync(0xffffffffu, lsum1, 1);
    lsum1 += __shfl_xor_sync(0xffffffffu, lsum1, 2);
    float inv[2] = {1.0f / lsum0, 1.0f / lsum1};

    #pragma unroll
    for (int hf = 0; hf < 2; hf++) {
        int row = q0 + wid * 16 + rq + hf * 8;
        size_t base = ((size_t)(b * N_ + row)) * C_ + h * D_;
        #pragma unroll
        for (int j = 0; j < 8; j++) {
            int c = j * 8 + 2 * cq;
            float2 xv = *(const float2*)(x + base + c);
            float2 o;
            o.x = oacc[j][2 * hf]     * inv[hf] + xv.x;
            o.y = oacc[j][2 * hf + 1] * inv[hf] + xv.y;
            *(float2*)(x2 + base + c) = o;
        }
    }
}

// ---------------- LayerNorm: warp per row, shuffle-only ----------------
__global__ __launch_bounds__(256) void ln_kernel(const float* __restrict__ x,
                                                 const float* __restrict__ g,
                                                 const float* __restrict__ b,
                                                 __half* __restrict__ out) {
    int w = threadIdx.x >> 5, lane = threadIdx.x & 31;
    size_t row = (size_t)blockIdx.x * 8 + w;
    const float* xr = x + row * C_;

    float4 v[4];
    float s = 0.f;
    #pragma unroll
    for (int k = 0; k < 4; k++) {
        v[k] = *(const float4*)(xr + (lane + k * 32) * 4);
        s += (v[k].x + v[k].y) + (v[k].z + v[k].w);
    }
    #pragma unroll
    for (int o = 16; o > 0; o >>= 1) s += __shfl_xor_sync(0xffffffffu, s, o);
    float mu = s * (1.0f / C_);

    float t = 0.f;
    #pragma unroll
    for (int k = 0; k < 4; k++) {
        float dx = v[k].x - mu, dy = v[k].y - mu, dz = v[k].z - mu, dw = v[k].w - mu;
        t += dx * dx + dy * dy + dz * dz + dw * dw;
    }
    #pragma unroll
    for (int o = 16; o > 0; o >>= 1) t += __shfl_xor_sync(0xffffffffu, t, o);
    float rstd = rsqrtf(t * (1.0f / C_) + EPS_);

    __half* orow = out + row * C_;
    #pragma unroll
    for (int k = 0; k < 4; k++) {
        int c = (lane + k * 32) * 4;
        float4 gv = *(const float4*)(g + c);
        float4 bv = *(const float4*)(b + c);
        uint2 o;
        o.x = packh2((v[k].x - mu) * rstd * gv.x + bv.x,
                     (v[k].y - mu) * rstd * gv.y + bv.y);
        o.y = packh2((v[k].z - mu) * rstd * gv.z + bv.z,
                     (v[k].w - mu) * rstd * gv.w + bv.w);
        *(uint2*)(orow + c) = o;
    }
}

// ---------------- merged f32 -> f16 weight convert ----------------
#define NW1 (3*C_*C_/4)
#define NW2 (C_*HID_/4)
#define NW3 (HID_*C_/4)
__global__ __launch_bounds__(256) void cvt3_kernel(
    const float* __restrict__ a, const float* __restrict__ bb,
    const float* __restrict__ c,
    __half* __restrict__ wa, __half* __restrict__ wb, __half* __restrict__ wc) {
    int idx = blockIdx.x * 256 + threadIdx.x;
    const float* src; __half* dst; int off;
    if (idx < NW1)            { src = a;  dst = wa; off = idx; }
    else if (idx < NW1 + NW2) { src = bb; dst = wb; off = idx - NW1; }
    else                      { src = c;  dst = wc; off = idx - NW1 - NW2; }
    float4 v = ((const float4*)src)[off];
    uint2 o;
    o.x = packh2(v.x, v.y);
    o.y = packh2(v.z, v.w);
    ((uint2*)dst)[off] = o;
}

// ---------------- launch ----------------
extern "C" void kernel_launch(void* const* d_in, const int* in_sizes, int n_in,
                              void* d_out, int out_size) {
    const float* x      = (const float*)d_in[0];
    const float* ln1_g  = (const float*)d_in[1];
    const float* ln1_b  = (const float*)d_in[2];
    const float* qkv_w  = (const float*)d_in[3];
    const float* qkv_b  = (const float*)d_in[4];
    const float* ln2_g  = (const float*)d_in[5];
    const float* ln2_b  = (const float*)d_in[6];
    const float* fc1_w  = (const float*)d_in[7];
    const float* fc1_b  = (const float*)d_in[8];
    const float* fc2_w  = (const float*)d_in[9];
    const float* fc2_b  = (const float*)d_in[10];
    float* out = (float*)d_out;

    __half *h, *qkv, *m1, *w1, *w2, *w3;
    float *x2;
    cudaGetSymbolAddress((void**)&h,   g_h);
    cudaGetSymbolAddress((void**)&qkv, g_qkv);
    cudaGetSymbolAddress((void**)&x2,  g_x2);
    cudaGetSymbolAddress((void**)&m1,  g_m1);
    cudaGetSymbolAddress((void**)&w1,  g_w1);
    cudaGetSymbolAddress((void**)&w2,  g_w2);
    cudaGetSymbolAddress((void**)&w3,  g_w3);

    // weight conversions (one launch)
    cvt3_kernel<<<(NW1 + NW2 + NW3) / 256, 256>>>(qkv_w, fc1_w, fc2_w, w1, w2, w3);
    // 1. LN1 -> h (f16)
    ln_kernel<<<BN_ / 8, 256>>>(x, ln1_g, ln1_b, h);
    // 2. qkv = h @ qkv_w + b   (f16 out)
    gemm_h<0><<<dim3(3 * C_ / 128, BN_ / 128), 256>>>(
        h, C_, w1, 3 * C_, qkv, 3 * C_, qkv_b, nullptr, C_);
    // 3-6. fused attention (q' combine inlined)
    flash_kernel<<<dim3(N_ / 128, BH_), 256>>>(qkv, x, x2);
    // 7. LN2 -> h (f16)
    ln_kernel<<<BN_ / 8, 256>>>(x2, ln2_g, ln2_b, h);
    // 8. m1 = gelu(h @ fc1_w + b)
    gemm_h<1><<<dim3(HID_ / 128, BN_ / 128), 256>>>(
        h, C_, w2, HID_, m1, HID_, fc1_b, nullptr, C_);
    // 9. out = x2 + m1 @ fc2_w + b
    gemm_h<2><<<dim3(C_ / 128, BN_ / 128), 256>>>(
        m1, HID_, w3, C_, out, C_, fc2_b, x2, HID_);
}

// round 7
// speedup vs baseline: 8.2652x; 1.0222x over previous
#include <cuda_runtime.h>
#include <cuda_fp16.h>
#include <math.h>
#include <stdint.h>

#define B_   4
#define N_   1536
#define C_   512
#define H_   8
#define D_   64
#define HID_ 1024
#define BN_  (B_*N_)    // 6144
#define BH_  (B_*H_)    // 32
#define EPS_ 1e-5f
#define LOG2E 1.4426950408889634f
#define SOFF  8.0f      // log2-domain softmax offset

// ---------------- scratch ----------------
__device__ __half g_h   [BN_*C_];
__device__ __half g_qkv [BN_*3*C_];
__device__ float  g_x2  [BN_*C_];
__device__ __half g_m1  [BN_*HID_];
__device__ __half g_w1  [C_*3*C_];
__device__ __half g_w2  [C_*HID_];
__device__ __half g_w3  [HID_*C_];

// ---------------- asm helpers ----------------
#define LDSM4(d0,d1,d2,d3,addr) \
    asm volatile("ldmatrix.sync.aligned.m8n8.x4.shared.b16 {%0,%1,%2,%3}, [%4];" \
        : "=r"(d0),"=r"(d1),"=r"(d2),"=r"(d3) : "r"(addr))
#define LDSM4T(d0,d1,d2,d3,addr) \
    asm volatile("ldmatrix.sync.aligned.m8n8.x4.trans.shared.b16 {%0,%1,%2,%3}, [%4];" \
        : "=r"(d0),"=r"(d1),"=r"(d2),"=r"(d3) : "r"(addr))

__device__ __forceinline__ void mma_f16(float c[4], uint32_t a0, uint32_t a1,
                                        uint32_t a2, uint32_t a3,
                                        uint32_t b0, uint32_t b1) {
    asm volatile(
        "mma.sync.aligned.m16n8k16.row.col.f32.f16.f16.f32 "
        "{%0,%1,%2,%3}, {%4,%5,%6,%7}, {%8,%9}, {%0,%1,%2,%3};"
        : "+f"(c[0]), "+f"(c[1]), "+f"(c[2]), "+f"(c[3])
        : "r"(a0), "r"(a1), "r"(a2), "r"(a3), "r"(b0), "r"(b1));
}
__device__ __forceinline__ uint32_t packh2(float lo, float hi) {
    __half2 h = __float22half2_rn(make_float2(lo, hi));
    return *(uint32_t*)&h;
}
__device__ __forceinline__ uint32_t ex2h2(uint32_t x) {
    uint32_t y; asm("ex2.approx.f16x2 %0, %1;" : "=r"(y) : "r"(x)); return y;
}
__device__ __forceinline__ uint32_t smem_u32(const void* p) {
    return (uint32_t)__cvta_generic_to_shared(p);
}
__device__ __forceinline__ void cp16(uint32_t dst, const void* src) {
    asm volatile("cp.async.cg.shared.global [%0], [%1], 16;" :: "r"(dst), "l"(src));
}
#define CP_COMMIT() asm volatile("cp.async.commit_group;" ::: "memory")
#define CP_WAIT(n)  asm volatile("cp.async.wait_group %0;" :: "n"(n) : "memory")

// ================= dense fp16 GEMM: C = epi(A @ B + bias) =================
#define ASTR 40
#define BSTR 136
template<int EPI>
__global__ __launch_bounds__(256, 2) void gemm_h(
    const __half* __restrict__ A, int lda,
    const __half* __restrict__ Bw, int ldb,
    void* __restrict__ Cout, int ldc,
    const float* __restrict__ bias,
    const float* __restrict__ resid, int K)
{
    __shared__ __align__(16) __half As[2][128 * ASTR];
    __shared__ __align__(16) __half Bs[2][32 * BSTR];

    int tid = threadIdx.x, wid = tid >> 5, lane = tid & 31;
    int wm = wid & 3, wn = wid >> 2;
    int m0 = blockIdx.y * 128, n0 = blockIdx.x * 128;

    float acc[2][8][4];
    #pragma unroll
    for (int i = 0; i < 2; i++)
        #pragma unroll
        for (int j = 0; j < 8; j++)
            #pragma unroll
            for (int q = 0; q < 4; q++) acc[i][j][q] = 0.f;

    int ar = (tid >> 2), ac = (tid & 3);
    int bk = (tid >> 4), bc = (tid & 15);
    const __half* Ag = A + (size_t)(m0 + ar) * lda + ac * 8;
    const __half* Bg = Bw + (size_t)bk * ldb + n0 + bc * 8;

    uint32_t dA0[2], dA1[2], dB0[2], dB1[2];
    #pragma unroll
    for (int s = 0; s < 2; s++) {
        dA0[s] = smem_u32(&As[s][ar * ASTR + ac * 8]);
        dA1[s] = smem_u32(&As[s][(ar + 64) * ASTR + ac * 8]);
        dB0[s] = smem_u32(&Bs[s][bk * BSTR + bc * 8]);
        dB1[s] = smem_u32(&Bs[s][(bk + 16) * BSTR + bc * 8]);
    }
    int T = K >> 5;
    {
        cp16(dA0[0], Ag);  cp16(dA1[0], Ag + (size_t)64 * lda);
        cp16(dB0[0], Bg);  cp16(dB1[0], Bg + (size_t)16 * ldb);
        CP_COMMIT();
        cp16(dA0[1], Ag + 32);  cp16(dA1[1], Ag + (size_t)64 * lda + 32);
        cp16(dB0[1], Bg + (size_t)32 * ldb);  cp16(dB1[1], Bg + (size_t)48 * ldb);
        CP_COMMIT();
    }

    int l15 = lane & 15, lhi = lane >> 4;
    for (int kt = 0; kt < T; kt++) {
        int buf = kt & 1;
        if (kt < T - 1) CP_WAIT(1); else CP_WAIT(0);
        __syncthreads();

        uint32_t sA = smem_u32(&As[buf][0]);
        uint32_t sB = smem_u32(&Bs[buf][0]);
        uint32_t af[2][2][4];
        #pragma unroll
        for (int i = 0; i < 2; i++) {
            uint32_t base = sA + ((wm * 32 + i * 16 + l15) * ASTR + lhi * 8) * 2;
            #pragma unroll
            for (int s = 0; s < 2; s++)
                LDSM4(af[i][s][0], af[i][s][1], af[i][s][2], af[i][s][3],
                      base + s * 32);
        }
        #pragma unroll
        for (int s = 0; s < 2; s++) {
            uint32_t bbase = sB + ((s * 16 + l15) * BSTR + wn * 64 + lhi * 8) * 2;
            #pragma unroll
            for (int jj = 0; jj < 4; jj++) {
                uint32_t b0, b1, b2, b3;
                LDSM4T(b0, b1, b2, b3, bbase + jj * 32);
                #pragma unroll
                for (int i = 0; i < 2; i++) {
                    mma_f16(acc[i][2 * jj],     af[i][s][0], af[i][s][1], af[i][s][2], af[i][s][3], b0, b1);
                    mma_f16(acc[i][2 * jj + 1], af[i][s][0], af[i][s][1], af[i][s][2], af[i][s][3], b2, b3);
                }
            }
        }
        __syncthreads();
        if (kt + 2 < T) {
            const __half* Ag2 = Ag + (kt + 2) * 32;
            const __half* Bg2 = Bg + (size_t)(kt + 2) * 32 * ldb;
            cp16(dA0[buf], Ag2);  cp16(dA1[buf], Ag2 + (size_t)64 * lda);
            cp16(dB0[buf], Bg2);  cp16(dB1[buf], Bg2 + (size_t)16 * ldb);
            CP_COMMIT();
        }
    }

    int rq = lane >> 2, cq = lane & 3;
    #pragma unroll
    for (int i = 0; i < 2; i++) {
        #pragma unroll
        for (int half = 0; half < 2; half++) {
            size_t r = (size_t)(m0 + wm * 32 + i * 16 + rq + half * 8);
            #pragma unroll
            for (int j = 0; j < 8; j++) {
                int c = n0 + wn * 64 + j * 8 + 2 * cq;
                float v0 = acc[i][j][half * 2 + 0];
                float v1 = acc[i][j][half * 2 + 1];
                if (EPI == 0) {
                    v0 += bias[c]; v1 += bias[c + 1];
                    *(uint32_t*)((__half*)Cout + r * ldc + c) = packh2(v0, v1);
                } else if (EPI == 1) {
                    v0 += bias[c]; v1 += bias[c + 1];
                    v0 = 0.5f * v0 * (1.0f + erff(v0 * 0.70710678118654752f));
                    v1 = 0.5f * v1 * (1.0f + erff(v1 * 0.70710678118654752f));
                    *(uint32_t*)((__half*)Cout + r * ldc + c) = packh2(v0, v1);
                } else {
                    const float* rr = resid + r * ldc;
                    float2 o;
                    o.x = v0 + bias[c]     + rr[c];
                    o.y = v1 + bias[c + 1] + rr[c + 1];
                    *(float2*)((float*)Cout + r * ldc + c) = o;
                }
            }
        }
    }
}

// ================= fused flash attention =================
// x2 = x + softmax(q' k^T) v ; q' combine inlined; log2 domain, offset -SOFF.
// 3-stage KV ring, single __syncthreads per chunk; row sums via ones-column MMA.
#define FSTR 72
struct __align__(16) FlashSmem {
    union {
        __half q[128 * FSTR];          // prologue only (18432 B)
        __half kv[3][2][32 * FSTR];    // [stage][K/V][row] (27648 B)
    };
};
__global__ __launch_bounds__(256, 2) void flash_kernel(
    const __half* __restrict__ qkv,
    const float* __restrict__ x, float* __restrict__ x2)
{
    __shared__ FlashSmem fs;

    int tid = threadIdx.x, wid = tid >> 5, lane = tid & 31;
    int bh = blockIdx.y, b = bh >> 3, h = bh & 7;
    int q0 = blockIdx.x * 128;
    int seg = blockIdx.x >> 2;          // 0,1,2 (uniform per block)
    int l15 = lane & 15, lhi = lane >> 4;
    int rq = lane >> 2, cq = lane & 3;
    const float ksc = 0.125f * LOG2E;

    // ---- Q prologue: load + segment combine + scale -> smem ----
    {
        const __half* qbase = qkv + ((size_t)(b * N_ + q0)) * (3 * C_) + h * D_;
        #pragma unroll
        for (int it = 0; it < 4; it++) {
            int idx = tid + it * 256;
            int row = idx >> 3, c8 = (idx & 7) * 8;
            const __half* p0 = qbase + (size_t)row * (3 * C_) + c8;
            uint4 va = *(const uint4*)p0;
            __half2* ha = (__half2*)&va;
            float2 f[4];
            #pragma unroll
            for (int i = 0; i < 4; i++) f[i] = __half22float2(ha[i]);
            if (seg >= 1) {
                uint4 vb = *(const uint4*)(p0 - (size_t)512 * (3 * C_));
                __half2* hb = (__half2*)&vb;
                #pragma unroll
                for (int i = 0; i < 4; i++) {
                    float2 g2 = __half22float2(hb[i]);
                    f[i].x += 0.5f * g2.x; f[i].y += 0.5f * g2.y;
                }
            }
            if (seg >= 2) {
                uint4 vc = *(const uint4*)(p0 - (size_t)1024 * (3 * C_));
                __half2* hc = (__half2*)&vc;
                #pragma unroll
                for (int i = 0; i < 4; i++) {
                    float2 g2 = __half22float2(hc[i]);
                    f[i].x += 0.25f * g2.x; f[i].y += 0.25f * g2.y;
                }
            }
            uint4 o; uint32_t* op = (uint32_t*)&o;
            #pragma unroll
            for (int i = 0; i < 4; i++) op[i] = packh2(f[i].x * ksc, f[i].y * ksc);
            *(uint4*)&fs.q[row * FSTR + c8] = o;
        }
    }
    __syncthreads();

    uint32_t aq[4][4];
    {
        uint32_t base = smem_u32(&fs.q[0]) + ((wid * 16 + l15) * FSTR + lhi * 8) * 2;
        #pragma unroll
        for (int s = 0; s < 4; s++)
            LDSM4(aq[s][0], aq[s][1], aq[s][2], aq[s][3], base + s * 32);
    }
    __syncthreads();   // Q region free for KV reuse

    float oacc[8][4];
    #pragma unroll
    for (int j = 0; j < 8; j++)
        #pragma unroll
        for (int q = 0; q < 4; q++) oacc[j][q] = 0.f;
    float lacc[4] = {0.f, 0.f, 0.f, 0.f};
    const uint32_t ONES = 0x3C003C00u;   // (1.0h, 1.0h)

    const __half* qkvb = qkv + (size_t)(b * N_) * (3 * C_) + h * D_;

    #define KV_ISSUE(kc_, buf_) do {                                          \
        int _kb = (kc_) * 32;                                                 \
        _Pragma("unroll")                                                     \
        for (int it = 0; it < 2; it++) {                                      \
            int idx = tid + it * 256;                                         \
            int tens = idx >> 8;                                              \
            int row = (idx >> 3) & 31;                                        \
            int c = idx & 7;                                                  \
            cp16(smem_u32(&fs.kv[buf_][tens][row * FSTR + c * 8]),            \
                 qkvb + (size_t)(_kb + row) * (3 * C_)                        \
                      + (tens ? 2 * C_ : C_) + c * 8);                        \
        }                                                                     \
        CP_COMMIT();                                                          \
    } while (0)

    KV_ISSUE(0, 0);
    KV_ISSUE(1, 1);

    int buf = 0, nbuf = 2;
    for (int kc = 0; kc < 48; kc++) {
        if (kc < 47) CP_WAIT(1); else CP_WAIT(0);
        __syncthreads();
        // issue kc+2 into the stage consumed at kc-1 (all warps past it)
        if (kc + 2 < 48) KV_ISSUE(kc + 2, nbuf);

        uint32_t kbase = smem_u32(&fs.kv[buf][0][0])
            + ((((lane >> 4) & 1) * 8 + (lane & 7)) * FSTR + ((lane >> 3) & 1) * 8) * 2;
        uint32_t vbase = smem_u32(&fs.kv[buf][1][0]) + (l15 * FSTR + lhi * 8) * 2;

        // ---- S = Q K^T (log2 domain, offset -SOFF) ----
        float sacc[4][4];
        #pragma unroll
        for (int j = 0; j < 4; j++)
            #pragma unroll
            for (int q = 0; q < 4; q++) sacc[j][q] = -SOFF;
        #pragma unroll
        for (int s = 0; s < 4; s++) {
            #pragma unroll
            for (int jj = 0; jj < 2; jj++) {
                uint32_t b0, b1, b2, b3;
                LDSM4(b0, b1, b2, b3, kbase + jj * (16 * FSTR * 2) + s * 32);
                mma_f16(sacc[2 * jj],     aq[s][0], aq[s][1], aq[s][2], aq[s][3], b0, b1);
                mma_f16(sacc[2 * jj + 1], aq[s][0], aq[s][1], aq[s][2], aq[s][3], b2, b3);
            }
        }

        // ---- p = 2^s in f16x2 ----
        uint32_t ph[4][2];
        #pragma unroll
        for (int j = 0; j < 4; j++) {
            ph[j][0] = ex2h2(packh2(sacc[j][0], sacc[j][1]));
            ph[j][1] = ex2h2(packh2(sacc[j][2], sacc[j][3]));
        }

        // ---- row sums via ones-column MMA (f32 acc, cross-chunk) ----
        mma_f16(lacc, ph[0][0], ph[0][1], ph[1][0], ph[1][1], ONES, ONES);
        mma_f16(lacc, ph[2][0], ph[2][1], ph[3][0], ph[3][1], ONES, ONES);

        // ---- O += P V ----
        #pragma unroll
        for (int s = 0; s < 2; s++) {
            #pragma unroll
            for (int jj = 0; jj < 4; jj++) {
                uint32_t b0, b1, b2, b3;
                LDSM4T(b0, b1, b2, b3, vbase + s * (16 * FSTR * 2) + jj * 32);
                mma_f16(oacc[2 * jj],     ph[2 * s][0], ph[2 * s][1], ph[2 * s + 1][0], ph[2 * s + 1][1], b0, b1);
                mma_f16(oacc[2 * jj + 1], ph[2 * s][0], ph[2 * s][1], ph[2 * s + 1][0], ph[2 * s + 1][1], b2, b3);
            }
        }
        buf++;  if (buf == 3)  buf = 0;
        nbuf++; if (nbuf == 3) nbuf = 0;
    }

    float inv[2] = {1.0f / lacc[0], 1.0f / lacc[2]};

    #pragma unroll
    for (int hf = 0; hf < 2; hf++) {
        int row = q0 + wid * 16 + rq + hf * 8;
        size_t base = ((size_t)(b * N_ + row)) * C_ + h * D_;
        #pragma unroll
        for (int j = 0; j < 8; j++) {
            int c = j * 8 + 2 * cq;
            float2 xv = *(const float2*)(x + base + c);
            float2 o;
            o.x = oacc[j][2 * hf]     * inv[hf] + xv.x;
            o.y = oacc[j][2 * hf + 1] * inv[hf] + xv.y;
            *(float2*)(x2 + base + c) = o;
        }
    }
}

// ---------------- LayerNorm: warp per row, shuffle-only ----------------
__global__ __launch_bounds__(256) void ln_kernel(const float* __restrict__ x,
                                                 const float* __restrict__ g,
                                                 const float* __restrict__ b,
                                                 __half* __restrict__ out) {
    int w = threadIdx.x >> 5, lane = threadIdx.x & 31;
    size_t row = (size_t)blockIdx.x * 8 + w;
    const float* xr = x + row * C_;

    float4 v[4];
    float s = 0.f;
    #pragma unroll
    for (int k = 0; k < 4; k++) {
        v[k] = *(const float4*)(xr + (lane + k * 32) * 4);
        s += (v[k].x + v[k].y) + (v[k].z + v[k].w);
    }
    #pragma unroll
    for (int o = 16; o > 0; o >>= 1) s += __shfl_xor_sync(0xffffffffu, s, o);
    float mu = s * (1.0f / C_);

    float t = 0.f;
    #pragma unroll
    for (int k = 0; k < 4; k++) {
        float dx = v[k].x - mu, dy = v[k].y - mu, dz = v[k].z - mu, dw = v[k].w - mu;
        t += dx * dx + dy * dy + dz * dz + dw * dw;
    }
    #pragma unroll
    for (int o = 16; o > 0; o >>= 1) t += __shfl_xor_sync(0xffffffffu, t, o);
    float rstd = rsqrtf(t * (1.0f / C_) + EPS_);

    __half* orow = out + row * C_;
    #pragma unroll
    for (int k = 0; k < 4; k++) {
        int c = (lane + k * 32) * 4;
        float4 gv = *(const float4*)(g + c);
        float4 bv = *(const float4*)(b + c);
        uint2 o;
        o.x = packh2((v[k].x - mu) * rstd * gv.x + bv.x,
                     (v[k].y - mu) * rstd * gv.y + bv.y);
        o.y = packh2((v[k].z - mu) * rstd * gv.z + bv.z,
                     (v[k].w - mu) * rstd * gv.w + bv.w);
        *(uint2*)(orow + c) = o;
    }
}

// ---------------- merged f32 -> f16 weight convert ----------------
#define NW1 (3*C_*C_/4)
#define NW2 (C_*HID_/4)
#define NW3 (HID_*C_/4)
__global__ __launch_bounds__(256) void cvt3_kernel(
    const float* __restrict__ a, const float* __restrict__ bb,
    const float* __restrict__ c,
    __half* __restrict__ wa, __half* __restrict__ wb, __half* __restrict__ wc) {
    int idx = blockIdx.x * 256 + threadIdx.x;
    const float* src; __half* dst; int off;
    if (idx < NW1)            { src = a;  dst = wa; off = idx; }
    else if (idx < NW1 + NW2) { src = bb; dst = wb; off = idx - NW1; }
    else                      { src = c;  dst = wc; off = idx - NW1 - NW2; }
    float4 v = ((const float4*)src)[off];
    uint2 o;
    o.x = packh2(v.x, v.y);
    o.y = packh2(v.z, v.w);
    ((uint2*)dst)[off] = o;
}

// ---------------- launch ----------------
extern "C" void kernel_launch(void* const* d_in, const int* in_sizes, int n_in,
                              void* d_out, int out_size) {
    const float* x      = (const float*)d_in[0];
    const float* ln1_g  = (const float*)d_in[1];
    const float* ln1_b  = (const float*)d_in[2];
    const float* qkv_w  = (const float*)d_in[3];
    const float* qkv_b  = (const float*)d_in[4];
    const float* ln2_g  = (const float*)d_in[5];
    const float* ln2_b  = (const float*)d_in[6];
    const float* fc1_w  = (const float*)d_in[7];
    const float* fc1_b  = (const float*)d_in[8];
    const float* fc2_w  = (const float*)d_in[9];
    const float* fc2_b  = (const float*)d_in[10];
    float* out = (float*)d_out;

    __half *h, *qkv, *m1, *w1, *w2, *w3;
    float *x2;
    cudaGetSymbolAddress((void**)&h,   g_h);
    cudaGetSymbolAddress((void**)&qkv, g_qkv);
    cudaGetSymbolAddress((void**)&x2,  g_x2);
    cudaGetSymbolAddress((void**)&m1,  g_m1);
    cudaGetSymbolAddress((void**)&w1,  g_w1);
    cudaGetSymbolAddress((void**)&w2,  g_w2);
    cudaGetSymbolAddress((void**)&w3,  g_w3);

    cvt3_kernel<<<(NW1 + NW2 + NW3) / 256, 256>>>(qkv_w, fc1_w, fc2_w, w1, w2, w3);
    // 1. LN1 -> h (f16)
    ln_kernel<<<BN_ / 8, 256>>>(x, ln1_g, ln1_b, h);
    // 2. qkv = h @ qkv_w + b   (f16 out)
    gemm_h<0><<<dim3(3 * C_ / 128, BN_ / 128), 256>>>(
        h, C_, w1, 3 * C_, qkv, 3 * C_, qkv_b, nullptr, C_);
    // 3-6. fused attention
    flash_kernel<<<dim3(N_ / 128, BH_), 256>>>(qkv, x, x2);
    // 7. LN2 -> h (f16)
    ln_kernel<<<BN_ / 8, 256>>>(x2, ln2_g, ln2_b, h);
    // 8. m1 = gelu(h @ fc1_w + b)
    gemm_h<1><<<dim3(HID_ / 128, BN_ / 128), 256>>>(
        h, C_, w2, HID_, m1, HID_, fc1_b, nullptr, C_);
    // 9. out = x2 + m1 @ fc2_w + b
    gemm_h<2><<<dim3(C_ / 128, BN_ / 128), 256>>>(
        m1, HID_, w3, C_, out, C_, fc2_b, x2, HID_);
}

// round 8
// speedup vs baseline: 8.4511x; 1.0225x over previous
#include <cuda_runtime.h>
#include <cuda_fp16.h>
#include <math.h>
#include <stdint.h>

#define B_   4
#define N_   1536
#define C_   512
#define H_   8
#define D_   64
#define HID_ 1024
#define BN_  (B_*N_)    // 6144
#define BH_  (B_*H_)    // 32
#define EPS_ 1e-5f
#define LOG2E 1.4426950408889634f
#define SOFF  8.0f      // log2-domain softmax offset

// ---------------- scratch ----------------
__device__ __half g_h   [BN_*C_];
__device__ __half g_qkv [BN_*3*C_];
__device__ float  g_x2  [BN_*C_];
__device__ __half g_m1  [BN_*HID_];
__device__ __half g_w1  [C_*3*C_];
__device__ __half g_w2  [C_*HID_];
__device__ __half g_w3  [HID_*C_];

// ---------------- asm helpers ----------------
#define LDSM4(d0,d1,d2,d3,addr) \
    asm volatile("ldmatrix.sync.aligned.m8n8.x4.shared.b16 {%0,%1,%2,%3}, [%4];" \
        : "=r"(d0),"=r"(d1),"=r"(d2),"=r"(d3) : "r"(addr))
#define LDSM4T(d0,d1,d2,d3,addr) \
    asm volatile("ldmatrix.sync.aligned.m8n8.x4.trans.shared.b16 {%0,%1,%2,%3}, [%4];" \
        : "=r"(d0),"=r"(d1),"=r"(d2),"=r"(d3) : "r"(addr))

__device__ __forceinline__ void mma_f16(float c[4], uint32_t a0, uint32_t a1,
                                        uint32_t a2, uint32_t a3,
                                        uint32_t b0, uint32_t b1) {
    asm volatile(
        "mma.sync.aligned.m16n8k16.row.col.f32.f16.f16.f32 "
        "{%0,%1,%2,%3}, {%4,%5,%6,%7}, {%8,%9}, {%0,%1,%2,%3};"
        : "+f"(c[0]), "+f"(c[1]), "+f"(c[2]), "+f"(c[3])
        : "r"(a0), "r"(a1), "r"(a2), "r"(a3), "r"(b0), "r"(b1));
}
__device__ __forceinline__ uint32_t packh2(float lo, float hi) {
    __half2 h = __float22half2_rn(make_float2(lo, hi));
    return *(uint32_t*)&h;
}
__device__ __forceinline__ uint32_t ex2h2(uint32_t x) {
    uint32_t y; asm("ex2.approx.f16x2 %0, %1;" : "=r"(y) : "r"(x)); return y;
}
__device__ __forceinline__ uint32_t smem_u32(const void* p) {
    return (uint32_t)__cvta_generic_to_shared(p);
}
__device__ __forceinline__ void cp16(uint32_t dst, const void* src) {
    asm volatile("cp.async.cg.shared.global [%0], [%1], 16;" :: "r"(dst), "l"(src));
}
#define CP_COMMIT() asm volatile("cp.async.commit_group;" ::: "memory")
#define CP_WAIT(n)  asm volatile("cp.async.wait_group %0;" :: "n"(n) : "memory")

// ================= dense fp16 GEMM: C = epi(A @ B + bias) =================
// Tile MT x 128, kt=32, 8 warps. MT=128: warp 32x64 (occ 2). MT=64: warp 16x64 (occ 3).
#define ASTR 40
#define BSTR 136
template<int EPI, int MT>
__global__ __launch_bounds__(256, (MT == 128) ? 2 : 3) void gemm_h(
    const __half* __restrict__ A, int lda,
    const __half* __restrict__ Bw, int ldb,
    void* __restrict__ Cout, int ldc,
    const float* __restrict__ bias,
    const float* __restrict__ resid, int K)
{
    constexpr int MI = MT / 64;    // m-tiles (16 rows) per warp
    __shared__ __align__(16) __half As[2][MT * ASTR];
    __shared__ __align__(16) __half Bs[2][32 * BSTR];

    int tid = threadIdx.x, wid = tid >> 5, lane = tid & 31;
    int wm = wid & 3, wn = wid >> 2;
    int m0 = blockIdx.y * MT, n0 = blockIdx.x * 128;

    float acc[MI][8][4];
    #pragma unroll
    for (int i = 0; i < MI; i++)
        #pragma unroll
        for (int j = 0; j < 8; j++)
            #pragma unroll
            for (int q = 0; q < 4; q++) acc[i][j][q] = 0.f;

    int ar = (tid >> 2), ac = (tid & 3);
    int bk = (tid >> 4), bc = (tid & 15);
    const __half* Ag = A + (size_t)(m0 + ar) * lda + ac * 8;
    const __half* Bg = Bw + (size_t)bk * ldb + n0 + bc * 8;

    uint32_t dA0[2], dA1[2], dB0[2], dB1[2];
    #pragma unroll
    for (int s = 0; s < 2; s++) {
        dA0[s] = smem_u32(&As[s][ar * ASTR + ac * 8]);
        if (MT == 128) dA1[s] = smem_u32(&As[s][(ar + 64) * ASTR + ac * 8]);
        dB0[s] = smem_u32(&Bs[s][bk * BSTR + bc * 8]);
        dB1[s] = smem_u32(&Bs[s][(bk + 16) * BSTR + bc * 8]);
    }
    int T = K >> 5;
    {
        cp16(dA0[0], Ag);
        if (MT == 128) cp16(dA1[0], Ag + (size_t)64 * lda);
        cp16(dB0[0], Bg);  cp16(dB1[0], Bg + (size_t)16 * ldb);
        CP_COMMIT();
        cp16(dA0[1], Ag + 32);
        if (MT == 128) cp16(dA1[1], Ag + (size_t)64 * lda + 32);
        cp16(dB0[1], Bg + (size_t)32 * ldb);  cp16(dB1[1], Bg + (size_t)48 * ldb);
        CP_COMMIT();
    }

    int l15 = lane & 15, lhi = lane >> 4;
    for (int kt = 0; kt < T; kt++) {
        int buf = kt & 1;
        if (kt < T - 1) CP_WAIT(1); else CP_WAIT(0);
        __syncthreads();

        uint32_t sA = smem_u32(&As[buf][0]);
        uint32_t sB = smem_u32(&Bs[buf][0]);
        uint32_t af[MI][2][4];
        #pragma unroll
        for (int i = 0; i < MI; i++) {
            uint32_t base = sA + ((wm * (MT / 4) + i * 16 + l15) * ASTR + lhi * 8) * 2;
            #pragma unroll
            for (int s = 0; s < 2; s++)
                LDSM4(af[i][s][0], af[i][s][1], af[i][s][2], af[i][s][3],
                      base + s * 32);
        }
        #pragma unroll
        for (int s = 0; s < 2; s++) {
            uint32_t bbase = sB + ((s * 16 + l15) * BSTR + wn * 64 + lhi * 8) * 2;
            #pragma unroll
            for (int jj = 0; jj < 4; jj++) {
                uint32_t b0, b1, b2, b3;
                LDSM4T(b0, b1, b2, b3, bbase + jj * 32);
                #pragma unroll
                for (int i = 0; i < MI; i++) {
                    mma_f16(acc[i][2 * jj],     af[i][s][0], af[i][s][1], af[i][s][2], af[i][s][3], b0, b1);
                    mma_f16(acc[i][2 * jj + 1], af[i][s][0], af[i][s][1], af[i][s][2], af[i][s][3], b2, b3);
                }
            }
        }
        __syncthreads();
        if (kt + 2 < T) {
            const __half* Ag2 = Ag + (kt + 2) * 32;
            const __half* Bg2 = Bg + (size_t)(kt + 2) * 32 * ldb;
            cp16(dA0[buf], Ag2);
            if (MT == 128) cp16(dA1[buf], Ag2 + (size_t)64 * lda);
            cp16(dB0[buf], Bg2);  cp16(dB1[buf], Bg2 + (size_t)16 * ldb);
            CP_COMMIT();
        }
    }

    int rq = lane >> 2, cq = lane & 3;
    #pragma unroll
    for (int i = 0; i < MI; i++) {
        #pragma unroll
        for (int half = 0; half < 2; half++) {
            size_t r = (size_t)(m0 + wm * (MT / 4) + i * 16 + rq + half * 8);
            #pragma unroll
            for (int j = 0; j < 8; j++) {
                int c = n0 + wn * 64 + j * 8 + 2 * cq;
                float v0 = acc[i][j][half * 2 + 0];
                float v1 = acc[i][j][half * 2 + 1];
                if (EPI == 0) {
                    v0 += bias[c]; v1 += bias[c + 1];
                    *(uint32_t*)((__half*)Cout + r * ldc + c) = packh2(v0, v1);
                } else if (EPI == 1) {
                    v0 += bias[c]; v1 += bias[c + 1];
                    v0 = 0.5f * v0 * (1.0f + erff(v0 * 0.70710678118654752f));
                    v1 = 0.5f * v1 * (1.0f + erff(v1 * 0.70710678118654752f));
                    *(uint32_t*)((__half*)Cout + r * ldc + c) = packh2(v0, v1);
                } else {
                    const float* rr = resid + r * ldc;
                    float2 o;
                    o.x = v0 + bias[c]     + rr[c];
                    o.y = v1 + bias[c + 1] + rr[c + 1];
                    *(float2*)((float*)Cout + r * ldc + c) = o;
                }
            }
        }
    }
}

// ================= fused flash attention =================
// 64 q-rows per CTA, 4 warps, 5 CTAs/SM. 3-stage KV ring, single sync/chunk.
#define FSTR 72
struct __align__(16) FlashSmem {
    union {
        __half q[64 * FSTR];           // prologue only (9216 B)
        __half kv[3][2][32 * FSTR];    // [stage][K/V][row] (27648 B)
    };
};
__global__ __launch_bounds__(128, 5) void flash_kernel(
    const __half* __restrict__ qkv,
    const float* __restrict__ x, float* __restrict__ x2)
{
    __shared__ FlashSmem fs;

    int tid = threadIdx.x, wid = tid >> 5, lane = tid & 31;
    int bh = blockIdx.y, b = bh >> 3, h = bh & 7;
    int q0 = blockIdx.x * 64;
    int seg = blockIdx.x >> 3;          // 0,1,2 (uniform per block)
    int l15 = lane & 15, lhi = lane >> 4;
    int rq = lane >> 2, cq = lane & 3;
    const float ksc = 0.125f * LOG2E;

    // ---- Q prologue: load + segment combine + scale -> smem ----
    {
        const __half* qbase = qkv + ((size_t)(b * N_ + q0)) * (3 * C_) + h * D_;
        #pragma unroll
        for (int it = 0; it < 4; it++) {
            int idx = tid + it * 128;
            int row = idx >> 3, c8 = (idx & 7) * 8;
            const __half* p0 = qbase + (size_t)row * (3 * C_) + c8;
            uint4 va = *(const uint4*)p0;
            __half2* ha = (__half2*)&va;
            float2 f[4];
            #pragma unroll
            for (int i = 0; i < 4; i++) f[i] = __half22float2(ha[i]);
            if (seg >= 1) {
                uint4 vb = *(const uint4*)(p0 - (size_t)512 * (3 * C_));
                __half2* hb = (__half2*)&vb;
                #pragma unroll
                for (int i = 0; i < 4; i++) {
                    float2 g2 = __half22float2(hb[i]);
                    f[i].x += 0.5f * g2.x; f[i].y += 0.5f * g2.y;
                }
            }
            if (seg >= 2) {
                uint4 vc = *(const uint4*)(p0 - (size_t)1024 * (3 * C_));
                __half2* hc = (__half2*)&vc;
                #pragma unroll
                for (int i = 0; i < 4; i++) {
                    float2 g2 = __half22float2(hc[i]);
                    f[i].x += 0.25f * g2.x; f[i].y += 0.25f * g2.y;
                }
            }
            uint4 o; uint32_t* op = (uint32_t*)&o;
            #pragma unroll
            for (int i = 0; i < 4; i++) op[i] = packh2(f[i].x * ksc, f[i].y * ksc);
            *(uint4*)&fs.q[row * FSTR + c8] = o;
        }
    }
    __syncthreads();

    uint32_t aq[4][4];
    {
        uint32_t base = smem_u32(&fs.q[0]) + ((wid * 16 + l15) * FSTR + lhi * 8) * 2;
        #pragma unroll
        for (int s = 0; s < 4; s++)
            LDSM4(aq[s][0], aq[s][1], aq[s][2], aq[s][3], base + s * 32);
    }
    __syncthreads();   // Q region free for KV reuse

    float oacc[8][4];
    #pragma unroll
    for (int j = 0; j < 8; j++)
        #pragma unroll
        for (int q = 0; q < 4; q++) oacc[j][q] = 0.f;
    float lacc[4] = {0.f, 0.f, 0.f, 0.f};
    const uint32_t ONES = 0x3C003C00u;

    const __half* qkvb = qkv + (size_t)(b * N_) * (3 * C_) + h * D_;

    #define KV_ISSUE(kc_, buf_) do {                                          \
        int _kb = (kc_) * 32;                                                 \
        _Pragma("unroll")                                                     \
        for (int it = 0; it < 4; it++) {                                      \
            int idx = tid + it * 128;                                         \
            int tens = idx >> 8;                                              \
            int row = (idx >> 3) & 31;                                        \
            int c = idx & 7;                                                  \
            cp16(smem_u32(&fs.kv[buf_][tens][row * FSTR + c * 8]),            \
                 qkvb + (size_t)(_kb + row) * (3 * C_)                        \
                      + (tens ? 2 * C_ : C_) + c * 8);                        \
        }                                                                     \
        CP_COMMIT();                                                          \
    } while (0)

    KV_ISSUE(0, 0);
    KV_ISSUE(1, 1);

    int buf = 0, nbuf = 2;
    for (int kc = 0; kc < 48; kc++) {
        if (kc < 47) CP_WAIT(1); else CP_WAIT(0);
        __syncthreads();
        if (kc + 2 < 48) KV_ISSUE(kc + 2, nbuf);

        uint32_t kbase = smem_u32(&fs.kv[buf][0][0])
            + ((((lane >> 4) & 1) * 8 + (lane & 7)) * FSTR + ((lane >> 3) & 1) * 8) * 2;
        uint32_t vbase = smem_u32(&fs.kv[buf][1][0]) + (l15 * FSTR + lhi * 8) * 2;

        // ---- S = Q K^T (log2 domain, offset -SOFF) ----
        float sacc[4][4];
        #pragma unroll
        for (int j = 0; j < 4; j++)
            #pragma unroll
            for (int q = 0; q < 4; q++) sacc[j][q] = -SOFF;
        #pragma unroll
        for (int s = 0; s < 4; s++) {
            #pragma unroll
            for (int jj = 0; jj < 2; jj++) {
                uint32_t b0, b1, b2, b3;
                LDSM4(b0, b1, b2, b3, kbase + jj * (16 * FSTR * 2) + s * 32);
                mma_f16(sacc[2 * jj],     aq[s][0], aq[s][1], aq[s][2], aq[s][3], b0, b1);
                mma_f16(sacc[2 * jj + 1], aq[s][0], aq[s][1], aq[s][2], aq[s][3], b2, b3);
            }
        }

        // ---- p = 2^s in f16x2 ----
        uint32_t ph[4][2];
        #pragma unroll
        for (int j = 0; j < 4; j++) {
            ph[j][0] = ex2h2(packh2(sacc[j][0], sacc[j][1]));
            ph[j][1] = ex2h2(packh2(sacc[j][2], sacc[j][3]));
        }

        // ---- row sums via ones-column MMA ----
        mma_f16(lacc, ph[0][0], ph[0][1], ph[1][0], ph[1][1], ONES, ONES);
        mma_f16(lacc, ph[2][0], ph[2][1], ph[3][0], ph[3][1], ONES, ONES);

        // ---- O += P V ----
        #pragma unroll
        for (int s = 0; s < 2; s++) {
            #pragma unroll
            for (int jj = 0; jj < 4; jj++) {
                uint32_t b0, b1, b2, b3;
                LDSM4T(b0, b1, b2, b3, vbase + s * (16 * FSTR * 2) + jj * 32);
                mma_f16(oacc[2 * jj],     ph[2 * s][0], ph[2 * s][1], ph[2 * s + 1][0], ph[2 * s + 1][1], b0, b1);
                mma_f16(oacc[2 * jj + 1], ph[2 * s][0], ph[2 * s][1], ph[2 * s + 1][0], ph[2 * s + 1][1], b2, b3);
            }
        }
        buf++;  if (buf == 3)  buf = 0;
        nbuf++; if (nbuf == 3) nbuf = 0;
    }

    float inv[2] = {1.0f / lacc[0], 1.0f / lacc[2]};

    #pragma unroll
    for (int hf = 0; hf < 2; hf++) {
        int row = q0 + wid * 16 + rq + hf * 8;
        size_t base = ((size_t)(b * N_ + row)) * C_ + h * D_;
        #pragma unroll
        for (int j = 0; j < 8; j++) {
            int c = j * 8 + 2 * cq;
            float2 xv = *(const float2*)(x + base + c);
            float2 o;
            o.x = oacc[j][2 * hf]     * inv[hf] + xv.x;
            o.y = oacc[j][2 * hf + 1] * inv[hf] + xv.y;
            *(float2*)(x2 + base + c) = o;
        }
    }
}

// ---------------- LayerNorm: warp per row, shuffle-only ----------------
__global__ __launch_bounds__(256) void ln_kernel(const float* __restrict__ x,
                                                 const float* __restrict__ g,
                                                 const float* __restrict__ b,
                                                 __half* __restrict__ out) {
    int w = threadIdx.x >> 5, lane = threadIdx.x & 31;
    size_t row = (size_t)blockIdx.x * 8 + w;
    const float* xr = x + row * C_;

    float4 v[4];
    float s = 0.f;
    #pragma unroll
    for (int k = 0; k < 4; k++) {
        v[k] = *(const float4*)(xr + (lane + k * 32) * 4);
        s += (v[k].x + v[k].y) + (v[k].z + v[k].w);
    }
    #pragma unroll
    for (int o = 16; o > 0; o >>= 1) s += __shfl_xor_sync(0xffffffffu, s, o);
    float mu = s * (1.0f / C_);

    float t = 0.f;
    #pragma unroll
    for (int k = 0; k < 4; k++) {
        float dx = v[k].x - mu, dy = v[k].y - mu, dz = v[k].z - mu, dw = v[k].w - mu;
        t += dx * dx + dy * dy + dz * dz + dw * dw;
    }
    #pragma unroll
    for (int o = 16; o > 0; o >>= 1) t += __shfl_xor_sync(0xffffffffu, t, o);
    float rstd = rsqrtf(t * (1.0f / C_) + EPS_);

    __half* orow = out + row * C_;
    #pragma unroll
    for (int k = 0; k < 4; k++) {
        int c = (lane + k * 32) * 4;
        float4 gv = *(const float4*)(g + c);
        float4 bv = *(const float4*)(b + c);
        uint2 o;
        o.x = packh2((v[k].x - mu) * rstd * gv.x + bv.x,
                     (v[k].y - mu) * rstd * gv.y + bv.y);
        o.y = packh2((v[k].z - mu) * rstd * gv.z + bv.z,
                     (v[k].w - mu) * rstd * gv.w + bv.w);
        *(uint2*)(orow + c) = o;
    }
}

// ---------------- merged f32 -> f16 weight convert ----------------
#define NW1 (3*C_*C_/4)
#define NW2 (C_*HID_/4)
#define NW3 (HID_*C_/4)
__global__ __launch_bounds__(256) void cvt3_kernel(
    const float* __restrict__ a, const float* __restrict__ bb,
    const float* __restrict__ c,
    __half* __restrict__ wa, __half* __restrict__ wb, __half* __restrict__ wc) {
    int idx = blockIdx.x * 256 + threadIdx.x;
    const float* src; __half* dst; int off;
    if (idx < NW1)            { src = a;  dst = wa; off = idx; }
    else if (idx < NW1 + NW2) { src = bb; dst = wb; off = idx - NW1; }
    else                      { src = c;  dst = wc; off = idx - NW1 - NW2; }
    float4 v = ((const float4*)src)[off];
    uint2 o;
    o.x = packh2(v.x, v.y);
    o.y = packh2(v.z, v.w);
    ((uint2*)dst)[off] = o;
}

// ---------------- launch ----------------
extern "C" void kernel_launch(void* const* d_in, const int* in_sizes, int n_in,
                              void* d_out, int out_size) {
    const float* x      = (const float*)d_in[0];
    const float* ln1_g  = (const float*)d_in[1];
    const float* ln1_b  = (const float*)d_in[2];
    const float* qkv_w  = (const float*)d_in[3];
    const float* qkv_b  = (const float*)d_in[4];
    const float* ln2_g  = (const float*)d_in[5];
    const float* ln2_b  = (const float*)d_in[6];
    const float* fc1_w  = (const float*)d_in[7];
    const float* fc1_b  = (const float*)d_in[8];
    const float* fc2_w  = (const float*)d_in[9];
    const float* fc2_b  = (const float*)d_in[10];
    float* out = (float*)d_out;

    __half *h, *qkv, *m1, *w1, *w2, *w3;
    float *x2;
    cudaGetSymbolAddress((void**)&h,   g_h);
    cudaGetSymbolAddress((void**)&qkv, g_qkv);
    cudaGetSymbolAddress((void**)&x2,  g_x2);
    cudaGetSymbolAddress((void**)&m1,  g_m1);
    cudaGetSymbolAddress((void**)&w1,  g_w1);
    cudaGetSymbolAddress((void**)&w2,  g_w2);
    cudaGetSymbolAddress((void**)&w3,  g_w3);

    cvt3_kernel<<<(NW1 + NW2 + NW3) / 256, 256>>>(qkv_w, fc1_w, fc2_w, w1, w2, w3);
    // 1. LN1 -> h (f16)
    ln_kernel<<<BN_ / 8, 256>>>(x, ln1_g, ln1_b, h);
    // 2. qkv = h @ qkv_w + b
    gemm_h<0, 128><<<dim3(3 * C_ / 128, BN_ / 128), 256>>>(
        h, C_, w1, 3 * C_, qkv, 3 * C_, qkv_b, nullptr, C_);
    // 3-6. fused attention (64-row q-tiles, 5 CTAs/SM)
    flash_kernel<<<dim3(N_ / 64, BH_), 128>>>(qkv, x, x2);
    // 7. LN2 -> h (f16)
    ln_kernel<<<BN_ / 8, 256>>>(x2, ln2_g, ln2_b, h);
    // 8. m1 = gelu(h @ fc1_w + b)
    gemm_h<1, 128><<<dim3(HID_ / 128, BN_ / 128), 256>>>(
        h, C_, w2, HID_, m1, HID_, fc1_b, nullptr, C_);
    // 9. out = x2 + m1 @ fc2_w + b   (64-row tiles, 3 CTAs/SM)
    gemm_h<2, 64><<<dim3(C_ / 128, BN_ / 64), 256>>>(
        m1, HID_, w3, C_, out, C_, fc2_b, x2, HID_);
}